// round 13
// baseline (speedup 1.0000x reference)
#include <cuda_runtime.h>
#include <cuda_bf16.h>
#include <math.h>
#include <stdint.h>

constexpr int CB = 2, CS = 1024, CD = 1024;
constexpr int CH = 16, CKV = 4, CHD = 64;
constexpr int CE = 8, CF = 2048;
constexpr int CT = CB * CS;
constexpr float CEPS = 1e-6f;

__device__ __nv_bfloat16 g_xnbh[CT * CD], g_xnbl[CT * CD];
__device__ float g_q  [CT * CH  * CHD];
__device__ float g_k  [CT * CKV * CHD];
__device__ __nv_bfloat16 g_kbh[CT * CKV * CHD], g_kbl[CT * CKV * CHD];
__device__ __nv_bfloat16 g_vbTh[CB * CKV * CHD * CS], g_vbTl[CB * CKV * CHD * CS];
__device__ __nv_bfloat16 g_atthb[CT * CH * CHD], g_attlb[CT * CH * CHD];
__device__ float g_h1 [CT * CD];
__device__ float g_hn [CT * CD];
__device__ __nv_bfloat16 g_hnb[CT * CD];
__device__ int   g_cnt [CE];
__device__ int   g_tok [CE * CT];
__device__ float g_wsl [CE * CT];
__device__ int   g_slot[CT * 2];
__device__ __nv_bfloat16 g_hexpb[(size_t)CE * CT * CF];
__device__ float g_y   [(size_t)CE * CT * CD];
__device__ __nv_bfloat16 g_w1b[(size_t)CE * CF * CD];
__device__ __nv_bfloat16 g_w3b[(size_t)CE * CF * CD];
__device__ __nv_bfloat16 g_w2b[(size_t)CE * CD * CF];
__device__ __nv_bfloat16 g_wqTh[CD * CD],  g_wqTl[CD * CD];
__device__ __nv_bfloat16 g_wkTh[256 * CD], g_wkTl[256 * CD];
__device__ __nv_bfloat16 g_wvTh[256 * CD], g_wvTl[256 * CD];
__device__ __nv_bfloat16 g_woTh[CD * CD],  g_woTl[CD * CD];

#define U32(x) __float_as_uint(x)
#define MMAB(c, a, b0, b1) \
    asm volatile("mma.sync.aligned.m16n8k16.row.col.f32.bf16.bf16.f32 " \
        "{%0,%1,%2,%3}, {%4,%5,%6,%7}, {%8,%9}, {%0,%1,%2,%3};" \
        : "+f"((c)[0]), "+f"((c)[1]), "+f"((c)[2]), "+f"((c)[3]) \
        : "r"((a)[0]), "r"((a)[1]), "r"((a)[2]), "r"((a)[3]), "r"(b0), "r"(b1))

__device__ __forceinline__ void cpa16(uint32_t d, const void* s) {
    asm volatile("cp.async.ca.shared.global [%0], [%1], 16;" :: "r"(d), "l"(s));
}
#define CPC  asm volatile("cp.async.commit_group;")
#define CPW(n) asm volatile("cp.async.wait_group %0;" :: "n"(n))

__device__ __forceinline__ uint32_t packbf(float a, float b) {
    __nv_bfloat162 t = __floats2bfloat162_rn(a, b);
    return *(uint32_t*)&t;
}
__device__ __forceinline__ float bfl(__nv_bfloat16 h) { return __bfloat162float(h); }

// k-pair interleave permutation (within each 32-element block)
__device__ __forceinline__ int perm32(int d) {
    int pair = (d >> 1) & 15, e = d & 1;
    int p8 = pair & 7;
    int npos = (p8 < 4) ? (2 * p8) : (2 * (p8 - 4) + 1);
    int newpair = (pair & 8) | npos;
    return (d & ~31) | (newpair << 1) | e;
}

constexpr int MA_STG = 128 * 40;
constexpr int MB_STG = 64 * 40;
constexpr int PMA = 128 * 48;
constexpr int PMB = 64 * 48;

// ------------- bf16 permuted-layout core (MoE): LDS.64 fragments -------------
template<bool DUAL>
__device__ __forceinline__ void mma_core_bf16p(
    const __nv_bfloat16* pA0, const __nv_bfloat16* pA1,
    const __nv_bfloat16* pB1, const __nv_bfloat16* pB3,
    int K, __nv_bfloat16* sA, __nv_bfloat16* sB1, __nv_bfloat16* sB3, int tid,
    float c1[2][4][4], float c3[2][4][4])
{
    const int lane = tid & 31, wid = tid >> 5, grp = lane >> 2, tig = lane & 3;
    const int wm = (wid >> 1) * 32, wn = (wid & 1) * 32;
    uint32_t aA0 = (uint32_t)__cvta_generic_to_shared(sA) + (tid >> 2) * 96 + (tid & 3) * 16;
    uint32_t aA1 = aA0 + 64 * 96;
    uint32_t aB1 = (uint32_t)__cvta_generic_to_shared(sB1) + (tid >> 2) * 96 + (tid & 3) * 16;
    uint32_t aB3 = DUAL ? (uint32_t)__cvta_generic_to_shared(sB3) + (tid >> 2) * 96 + (tid & 3) * 16 : 0u;

    cpa16(aA0, pA0);
    cpa16(aA1, pA1);
    cpa16(aB1, pB1);
    if (DUAL) cpa16(aB3, pB3);
    CPC;

    int nt = K / 32;
    for (int t = 0; t < nt; ++t) {
        if (t + 1 < nt) {
            int k0 = (t + 1) * 32, st = (t + 1) & 1;
            cpa16(aA0 + st * (PMA * 2), pA0 + k0);
            cpa16(aA1 + st * (PMA * 2), pA1 + k0);
            cpa16(aB1 + st * (PMB * 2), pB1 + k0);
            if (DUAL) cpa16(aB3 + st * (PMB * 2), pB3 + k0);
            CPC; CPW(1);
        } else { CPW(0); }
        __syncthreads();
        const uint32_t* AU  = (const uint32_t*)(sA  + (t & 1) * PMA);
        const uint32_t* B1U = (const uint32_t*)(sB1 + (t & 1) * PMB);
        const uint32_t* B3U = (const uint32_t*)(sB3 + (t & 1) * PMB);
        #pragma unroll
        for (int ks = 0; ks < 2; ++ks) {
            int po = ks * 8 + 2 * tig;
            uint32_t a[2][4];
            #pragma unroll
            for (int i = 0; i < 2; ++i) {
                int r = wm + 16 * i + grp;
                uint2 t0 = *(const uint2*)&AU[r * 24 + po];
                uint2 t1 = *(const uint2*)&AU[(r + 8) * 24 + po];
                a[i][0] = t0.x; a[i][2] = t0.y;
                a[i][1] = t1.x; a[i][3] = t1.y;
            }
            #pragma unroll
            for (int j = 0; j < 4; ++j) {
                int n = wn + 8 * j + grp;
                uint2 b = *(const uint2*)&B1U[n * 24 + po];
                MMAB(c1[0][j], a[0], b.x, b.y);
                MMAB(c1[1][j], a[1], b.x, b.y);
                if (DUAL) {
                    uint2 d2 = *(const uint2*)&B3U[n * 24 + po];
                    MMAB(c3[0][j], a[0], d2.x, d2.y);
                    MMAB(c3[1][j], a[1], d2.x, d2.y);
                }
            }
        }
        __syncthreads();
    }
}

// ------------- bf16 3-term core (qkv/oproj) -------------
__device__ __forceinline__ void mma_core_bf16_3(
    const __nv_bfloat16* pAh0, const __nv_bfloat16* pAh1,
    const __nv_bfloat16* pAl0, const __nv_bfloat16* pAl1,
    const __nv_bfloat16* pBh, const __nv_bfloat16* pBl,
    int K, __nv_bfloat16* sm, int tid, float c[2][4][4])
{
    __nv_bfloat16* sAh = sm;
    __nv_bfloat16* sAl = sAh + 2 * MA_STG;
    __nv_bfloat16* sBh = sAl + 2 * MA_STG;
    __nv_bfloat16* sBl = sBh + 2 * MB_STG;
    const int lane = tid & 31, wid = tid >> 5, grp = lane >> 2, tig = lane & 3;
    const int wm = (wid >> 1) * 32, wn = (wid & 1) * 32;
    uint32_t off = (tid >> 2) * 80 + (tid & 3) * 16;
    uint32_t aAh0 = (uint32_t)__cvta_generic_to_shared(sAh) + off, aAh1 = aAh0 + 64 * 80;
    uint32_t aAl0 = (uint32_t)__cvta_generic_to_shared(sAl) + off, aAl1 = aAl0 + 64 * 80;
    uint32_t aBh  = (uint32_t)__cvta_generic_to_shared(sBh) + off;
    uint32_t aBl  = (uint32_t)__cvta_generic_to_shared(sBl) + off;

    cpa16(aAh0, pAh0); cpa16(aAh1, pAh1);
    cpa16(aAl0, pAl0); cpa16(aAl1, pAl1);
    cpa16(aBh, pBh);   cpa16(aBl, pBl);
    CPC;

    int nt = K / 32;
    for (int t = 0; t < nt; ++t) {
        if (t + 1 < nt) {
            int k0 = (t + 1) * 32, st = (t + 1) & 1;
            cpa16(aAh0 + st * (MA_STG * 2), pAh0 + k0);
            cpa16(aAh1 + st * (MA_STG * 2), pAh1 + k0);
            cpa16(aAl0 + st * (MA_STG * 2), pAl0 + k0);
            cpa16(aAl1 + st * (MA_STG * 2), pAl1 + k0);
            cpa16(aBh  + st * (MB_STG * 2), pBh + k0);
            cpa16(aBl  + st * (MB_STG * 2), pBl + k0);
            CPC; CPW(1);
        } else { CPW(0); }
        __syncthreads();
        const uint32_t* AhU = (const uint32_t*)(sAh + (t & 1) * MA_STG);
        const uint32_t* AlU = (const uint32_t*)(sAl + (t & 1) * MA_STG);
        const uint32_t* BhU = (const uint32_t*)(sBh + (t & 1) * MB_STG);
        const uint32_t* BlU = (const uint32_t*)(sBl + (t & 1) * MB_STG);
        #pragma unroll
        for (int ks = 0; ks < 2; ++ks) {
            int po = ks * 8;
            uint32_t ah[2][4], al[2][4];
            #pragma unroll
            for (int i = 0; i < 2; ++i) {
                int r = wm + 16 * i + grp;
                ah[i][0] = AhU[r * 20 + po + tig];
                ah[i][1] = AhU[(r + 8) * 20 + po + tig];
                ah[i][2] = AhU[r * 20 + po + tig + 4];
                ah[i][3] = AhU[(r + 8) * 20 + po + tig + 4];
                al[i][0] = AlU[r * 20 + po + tig];
                al[i][1] = AlU[(r + 8) * 20 + po + tig];
                al[i][2] = AlU[r * 20 + po + tig + 4];
                al[i][3] = AlU[(r + 8) * 20 + po + tig + 4];
            }
            #pragma unroll
            for (int j = 0; j < 4; ++j) {
                int n = wn + 8 * j + grp;
                uint32_t bh0 = BhU[n * 20 + po + tig], bh1 = BhU[n * 20 + po + tig + 4];
                uint32_t bl0 = BlU[n * 20 + po + tig], bl1 = BlU[n * 20 + po + tig + 4];
                #pragma unroll
                for (int i = 0; i < 2; ++i) {
                    MMAB(c[i][j], ah[i], bh0, bh1);
                    MMAB(c[i][j], ah[i], bl0, bl1);
                    MMAB(c[i][j], al[i], bh0, bh1);
                }
            }
        }
        __syncthreads();
    }
}

// ---------------- MoE weight transpose (k-permuted), GRID-STRIDE small-grid ----------------
__global__ void transpose_w_gs(const float* __restrict__ src, __nv_bfloat16* __restrict__ dst,
                               int R, int C, int nE) {
    __shared__ float t[32][33];
    int tilesR = R >> 5, tilesC = C >> 5;
    int ntiles = nE * tilesR * tilesC;
    int tx = threadIdx.x & 31, ty = threadIdx.x >> 5;
    int ptx = perm32(tx);
    for (int tile = blockIdx.x; tile < ntiles; tile += gridDim.x) {
        int z = tile / (tilesR * tilesC);
        int rem = tile % (tilesR * tilesC);
        int ry = rem / tilesC, cx = rem % tilesC;
        const float* s = src + (size_t)z * R * C;
        __nv_bfloat16* d = dst + (size_t)z * R * C;
        int r0 = ry * 32, c0 = cx * 32;
        #pragma unroll
        for (int i = 0; i < 4; ++i) {
            int r = ty + i * 8;
            t[r][tx] = s[(size_t)(r0 + r) * C + c0 + tx];
        }
        __syncthreads();
        #pragma unroll
        for (int i = 0; i < 4; ++i) {
            int r = ty + i * 8;
            d[(size_t)(c0 + r) * R + r0 + ptx] = __float2bfloat16_rn(t[tx][r]);
        }
        __syncthreads();
    }
}

// qkv/o weights: unpermuted hi/lo split (full grid; gates qkv_b3)
__global__ void transpose_w_split(const float* __restrict__ src,
                                  __nv_bfloat16* __restrict__ dh, __nv_bfloat16* __restrict__ dl,
                                  int R, int C) {
    __shared__ float t[32][33];
    int r0 = blockIdx.y * 32, c0 = blockIdx.x * 32;
    int tx = threadIdx.x & 31, ty = threadIdx.x >> 5;
    #pragma unroll
    for (int i = 0; i < 4; ++i) {
        int r = ty + i * 8;
        t[r][tx] = src[(size_t)(r0 + r) * C + c0 + tx];
    }
    __syncthreads();
    #pragma unroll
    for (int i = 0; i < 4; ++i) {
        int r = ty + i * 8;
        float v = t[tx][r];
        __nv_bfloat16 h = __float2bfloat16_rn(v);
        size_t idx = (size_t)(c0 + r) * R + r0 + tx;
        dh[idx] = h;
        dl[idx] = __float2bfloat16_rn(v - __bfloat162float(h));
    }
}

// ---------------- RMSNorm producing bf16 hi/lo ----------------
__global__ void rmsnorm_split(const float* __restrict__ x, const float* __restrict__ w,
                              __nv_bfloat16* __restrict__ oh, __nv_bfloat16* __restrict__ ol) {
    int t = blockIdx.x;
    const float* xr = x + (size_t)t * CD;
    float ss = 0.f;
    for (int d = threadIdx.x; d < CD; d += 256) { float v = xr[d]; ss += v * v; }
    __shared__ float red[256];
    red[threadIdx.x] = ss;
    __syncthreads();
    for (int s = 128; s > 0; s >>= 1) {
        if (threadIdx.x < s) red[threadIdx.x] += red[threadIdx.x + s];
        __syncthreads();
    }
    __shared__ float rinv;
    if (threadIdx.x == 0) rinv = rsqrtf(red[0] * (1.f / CD) + CEPS);
    __syncthreads();
    for (int d = threadIdx.x; d < CD; d += 256) {
        float v = xr[d] * rinv * w[d];
        size_t idx = (size_t)t * CD + d;
        __nv_bfloat16 h = __float2bfloat16_rn(v);
        oh[idx] = h;
        ol[idx] = __float2bfloat16_rn(v - __bfloat162float(h));
    }
}

// ---------------- RMSNorm dual: exact fp32 (router) + k-permuted bf16 (MoE A) ----------------
__global__ void rmsnorm_dual(const float* __restrict__ x, const float* __restrict__ w,
                             float* __restrict__ out, __nv_bfloat16* __restrict__ outb) {
    int t = blockIdx.x;
    const float* xr = x + (size_t)t * CD;
    float ss = 0.f;
    for (int d = threadIdx.x; d < CD; d += 256) { float v = xr[d]; ss += v * v; }
    __shared__ float red[256];
    red[threadIdx.x] = ss;
    __syncthreads();
    for (int s = 128; s > 0; s >>= 1) {
        if (threadIdx.x < s) red[threadIdx.x] += red[threadIdx.x + s];
        __syncthreads();
    }
    __shared__ float rinv;
    if (threadIdx.x == 0) rinv = rsqrtf(red[0] * (1.f / CD) + CEPS);
    __syncthreads();
    for (int d = threadIdx.x; d < CD; d += 256) {
        float v = xr[d] * rinv * w[d];
        out[(size_t)t * CD + d] = v;
        outb[(size_t)t * CD + perm32(d)] = __float2bfloat16_rn(v);
    }
}

// ---------------- fused QKV projection (3-term bf16); V written transposed bf16 hi/lo ----
constexpr size_t B3_SMEM = (size_t)(4 * MA_STG + 4 * MB_STG) * 2;
__global__ __launch_bounds__(256) void qkv_b3() {
    extern __shared__ __nv_bfloat16 bsm[];
    int n0 = blockIdx.x * 64, m0 = blockIdx.y * 128, tid = threadIdx.x;
    const __nv_bfloat16 *Bh, *Bl; float* C; int ldc, nc; bool isV = false;
    if (n0 < 1024)      { Bh = g_wqTh; Bl = g_wqTl; C = g_q; ldc = 1024; nc = n0; }
    else if (n0 < 1280) { Bh = g_wkTh; Bl = g_wkTl; C = g_k; ldc = 256;  nc = n0 - 1024; }
    else                { Bh = g_wvTh; Bl = g_wvTl; C = nullptr; ldc = 256; nc = n0 - 1280; isV = true; }
    const __nv_bfloat16* pAh0 = g_xnbh + (size_t)(m0 + (tid >> 2)) * CD + (tid & 3) * 8;
    const __nv_bfloat16* pAh1 = pAh0 + (size_t)64 * CD;
    const __nv_bfloat16* pAl0 = g_xnbl + (size_t)(m0 + (tid >> 2)) * CD + (tid & 3) * 8;
    const __nv_bfloat16* pAl1 = pAl0 + (size_t)64 * CD;
    const __nv_bfloat16* pBh  = Bh + (size_t)(nc + (tid >> 2)) * CD + (tid & 3) * 8;
    const __nv_bfloat16* pBl  = Bl + (size_t)(nc + (tid >> 2)) * CD + (tid & 3) * 8;
    float c[2][4][4] = {};
    mma_core_bf16_3(pAh0, pAh1, pAl0, pAl1, pBh, pBl, CD, bsm, tid, c);
    int lane = tid & 31, wid = tid >> 5, grp = lane >> 2, tig = lane & 3;
    int wm = (wid >> 1) * 32, wn = (wid & 1) * 32;
    if (!isV) {
        #pragma unroll
        for (int i = 0; i < 2; ++i) {
            int r = m0 + wm + 16 * i + grp;
            #pragma unroll
            for (int j = 0; j < 4; ++j) {
                int cc = nc + wn + 8 * j + 2 * tig;
                *(float2*)&C[(size_t)r * ldc + cc]       = make_float2(c[i][j][0], c[i][j][1]);
                *(float2*)&C[(size_t)(r + 8) * ldc + cc] = make_float2(c[i][j][2], c[i][j][3]);
            }
        }
    } else {
        #pragma unroll
        for (int i = 0; i < 2; ++i) {
            #pragma unroll
            for (int j = 0; j < 4; ++j) {
                int cc = nc + wn + 8 * j + 2 * tig;
                #pragma unroll
                for (int u = 0; u < 4; ++u) {
                    int r = m0 + wm + 16 * i + grp + (u >> 1) * 8;
                    int ccc = cc + (u & 1);
                    float v = c[i][j][u];
                    int bb = r >> 10, ss = r & 1023;
                    size_t o = ((size_t)(bb * CKV + (ccc >> 6)) * CHD + (ccc & 63)) * CS + ss;
                    __nv_bfloat16 hv = __float2bfloat16_rn(v);
                    g_vbTh[o] = hv;
                    g_vbTl[o] = __float2bfloat16_rn(v - bfl(hv));
                }
            }
        }
    }
}

// ---------------- O projection + residual (3-term bf16) ----------------
__global__ __launch_bounds__(256) void oproj_b3(const float* __restrict__ Res) {
    extern __shared__ __nv_bfloat16 bsm[];
    int n0 = blockIdx.x * 64, m0 = blockIdx.y * 128, tid = threadIdx.x;
    const __nv_bfloat16* pAh0 = g_atthb + (size_t)(m0 + (tid >> 2)) * CD + (tid & 3) * 8;
    const __nv_bfloat16* pAh1 = pAh0 + (size_t)64 * CD;
    const __nv_bfloat16* pAl0 = g_attlb + (size_t)(m0 + (tid >> 2)) * CD + (tid & 3) * 8;
    const __nv_bfloat16* pAl1 = pAl0 + (size_t)64 * CD;
    const __nv_bfloat16* pBh  = g_woTh + (size_t)(n0 + (tid >> 2)) * CD + (tid & 3) * 8;
    const __nv_bfloat16* pBl  = g_woTl + (size_t)(n0 + (tid >> 2)) * CD + (tid & 3) * 8;
    float c[2][4][4] = {};
    mma_core_bf16_3(pAh0, pAh1, pAl0, pAl1, pBh, pBl, CD, bsm, tid, c);
    int lane = tid & 31, wid = tid >> 5, grp = lane >> 2, tig = lane & 3;
    int wm = (wid >> 1) * 32, wn = (wid & 1) * 32;
    #pragma unroll
    for (int i = 0; i < 2; ++i) {
        int r = m0 + wm + 16 * i + grp;
        #pragma unroll
        for (int j = 0; j < 4; ++j) {
            int cc = n0 + wn + 8 * j + 2 * tig;
            size_t i0 = (size_t)r * CD + cc, i1 = (size_t)(r + 8) * CD + cc;
            float2 r0 = *(const float2*)&Res[i0], r1 = *(const float2*)&Res[i1];
            *(float2*)&g_h1[i0] = make_float2(c[i][j][0] + r0.x, c[i][j][1] + r0.y);
            *(float2*)&g_h1[i1] = make_float2(c[i][j][2] + r1.x, c[i][j][3] + r1.y);
        }
    }
}

// ---------------- RoPE: q in-place fp32; k -> bf16 hi/lo ----------------
__global__ void rope_kernel(const int* __restrict__ pos_ids) {
    int idx = blockIdx.x * 256 + threadIdx.x;
    const int nq = CT * CH * 32, nk = CT * CKV * 32;
    if (idx >= nq + nk) return;
    if (idx < nq) {
        int i = idx & 31; int th = idx >> 5; int h = th % CH; int t = th / CH;
        float* base = g_q + ((size_t)t * CH + h) * CHD;
        float p = (float)pos_ids[t];
        float freq = expf(-(2.f * i / (float)CHD) * logf(10000.f));
        float ang = p * freq, cv = cosf(ang), sv = sinf(ang);
        float x0 = base[i], x1 = base[i + 32];
        base[i] = x0 * cv - x1 * sv;
        base[i + 32] = x1 * cv + x0 * sv;
    } else {
        int id2 = idx - nq;
        int i = id2 & 31; int th = id2 >> 5; int h = th % CKV; int t = th / CKV;
        size_t boff = ((size_t)t * CKV + h) * CHD;
        const float* base = g_k + boff;
        float p = (float)pos_ids[t];
        float freq = expf(-(2.f * i / (float)CHD) * logf(10000.f));
        float ang = p * freq, cv = cosf(ang), sv = sinf(ang);
        float x0 = base[i], x1 = base[i + 32];
        float y0 = x0 * cv - x1 * sv;
        float y1 = x1 * cv + x0 * sv;
        __nv_bfloat16 h0 = __float2bfloat16_rn(y0), h1 = __float2bfloat16_rn(y1);
        g_kbh[boff + i]      = h0;
        g_kbl[boff + i]      = __float2bfloat16_rn(y0 - bfl(h0));
        g_kbh[boff + i + 32] = h1;
        g_kbl[boff + i + 32] = __float2bfloat16_rn(y1 - bfl(h1));
    }
}

// ---------------- flash attention (round-11 cp.async version, unchanged) ----------------
constexpr int FL_STG = 64 * 72;
constexpr int FL_SMEM = 128 * 72 * 4 + 8 * FL_STG * 2;
__global__ __launch_bounds__(256) void flash_bf16() {
    extern __shared__ char fsm[];
    float* Qs = (float*)fsm;
    uint32_t* PhU = (uint32_t*)fsm;
    uint32_t* PlU = PhU + 128 * 36;
    __nv_bfloat16* Kh = (__nv_bfloat16*)(fsm + 128 * 72 * 4);
    __nv_bfloat16* Kl = Kh + 2 * FL_STG;
    __nv_bfloat16* Vh = Kl + 2 * FL_STG;
    __nv_bfloat16* Vl = Vh + 2 * FL_STG;

    int bh = blockIdx.x, qt = 7 - blockIdx.y;
    int b = bh >> 4, h = bh & 15, kvh = h >> 2;
    int tid = threadIdx.x, lane = tid & 31, warp = tid >> 5, grp = lane >> 2, tig = lane & 3;
    int rl0 = warp * 16 + grp;

    uint32_t aKh = (uint32_t)__cvta_generic_to_shared(Kh);
    uint32_t aKl = (uint32_t)__cvta_generic_to_shared(Kl);
    uint32_t aVh = (uint32_t)__cvta_generic_to_shared(Vh);
    uint32_t aVl = (uint32_t)__cvta_generic_to_shared(Vl);

    auto load_tile = [&](int kt, int st) {
        uint32_t so = st * (FL_STG * 2);
        #pragma unroll
        for (int it = 0; it < 2; ++it) {
            int idx = tid + it * 256;
            int n = idx >> 3, c8 = (idx & 7) * 8;
            uint32_t dsto = so + (uint32_t)(n * 144 + c8 * 2);
            size_t gk = ((size_t)(b * CS + kt * 64 + n) * CKV + kvh) * CHD + c8;
            size_t gv = ((size_t)(b * CKV + kvh) * CHD + n) * CS + kt * 64 + c8;
            cpa16(aKh + dsto, g_kbh + gk);
            cpa16(aKl + dsto, g_kbl + gk);
            cpa16(aVh + dsto, g_vbTh + gv);
            cpa16(aVl + dsto, g_vbTl + gv);
        }
    };

    #pragma unroll
    for (int it = 0; it < 8; ++it) {
        int idx = tid + it * 256;
        int r = idx >> 4, d4 = (idx & 15) * 4;
        float4 qv = *(const float4*)&g_q[((size_t)(b * CS + qt * 128 + r) * CH + h) * CHD + d4];
        Qs[r * 72 + d4]     = qv.x * 0.125f;
        Qs[r * 72 + d4 + 1] = qv.y * 0.125f;
        Qs[r * 72 + d4 + 2] = qv.z * 0.125f;
        Qs[r * 72 + d4 + 3] = qv.w * 0.125f;
    }
    load_tile(0, 0);
    CPC;
    __syncthreads();

    uint32_t qh[4][4], ql[4][4];
    #pragma unroll
    for (int ks = 0; ks < 4; ++ks)
        #pragma unroll
        for (int u = 0; u < 4; ++u) {
            int kk = ks * 16 + 2 * (tig + (u >> 1) * 4);
            int rr = rl0 + (u & 1) * 8;
            float x0 = Qs[rr * 72 + kk], x1 = Qs[rr * 72 + kk + 1];
            __nv_bfloat16 h0 = __float2bfloat16_rn(x0), h1 = __float2bfloat16_rn(x1);
            qh[ks][u] = packbf(bfl(h0), bfl(h1));
            ql[ks][u] = packbf(x0 - bfl(h0), x1 - bfl(h1));
        }

    float o[8][4] = {};
    float m0v = -INFINITY, m1v = -INFINITY, l0v = 0.f, l1v = 0.f;
    int ntiles = 2 * (qt + 1);

    for (int kt = 0; kt < ntiles; ++kt) {
        if (kt + 1 < ntiles) {
            load_tile(kt + 1, (kt + 1) & 1);
            CPC; CPW(1);
        } else { CPW(0); }
        __syncthreads();
        const uint32_t* KhU = (const uint32_t*)(Kh + (kt & 1) * FL_STG);
        const uint32_t* KlU = (const uint32_t*)(Kl + (kt & 1) * FL_STG);
        const uint32_t* VhU = (const uint32_t*)(Vh + (kt & 1) * FL_STG);
        const uint32_t* VlU = (const uint32_t*)(Vl + (kt & 1) * FL_STG);

        float s[8][4] = {};
        #pragma unroll
        for (int ks = 0; ks < 4; ++ks) {
            int po = ks * 8;
            #pragma unroll
            for (int j = 0; j < 8; ++j) {
                int n = 8 * j + grp;
                uint32_t bh0 = KhU[n * 36 + po + tig], bh1 = KhU[n * 36 + po + tig + 4];
                uint32_t bl0 = KlU[n * 36 + po + tig], bl1 = KlU[n * 36 + po + tig + 4];
                MMAB(s[j], qh[ks], bh0, bh1);
                MMAB(s[j], qh[ks], bl0, bl1);
                MMAB(s[j], ql[ks], bh0, bh1);
            }
        }
        if (kt >= 2 * qt) {
            int rg0 = qt * 128 + rl0;
            #pragma unroll
            for (int j = 0; j < 8; ++j) {
                int cg = kt * 64 + 8 * j + 2 * tig;
                if (cg     > rg0)     s[j][0] = -INFINITY;
                if (cg + 1 > rg0)     s[j][1] = -INFINITY;
                if (cg     > rg0 + 8) s[j][2] = -INFINITY;
                if (cg + 1 > rg0 + 8) s[j][3] = -INFINITY;
            }
        }
        float mx0 = -INFINITY, mx1 = -INFINITY;
        #pragma unroll
        for (int j = 0; j < 8; ++j) {
            mx0 = fmaxf(mx0, fmaxf(s[j][0], s[j][1]));
            mx1 = fmaxf(mx1, fmaxf(s[j][2], s[j][3]));
        }
        mx0 = fmaxf(mx0, __shfl_xor_sync(0xffffffffu, mx0, 1));
        mx0 = fmaxf(mx0, __shfl_xor_sync(0xffffffffu, mx0, 2));
        mx1 = fmaxf(mx1, __shfl_xor_sync(0xffffffffu, mx1, 1));
        mx1 = fmaxf(mx1, __shfl_xor_sync(0xffffffffu, mx1, 2));
        float mn0 = fmaxf(m0v, mx0), mn1 = fmaxf(m1v, mx1);
        float al0 = expf(m0v - mn0), al1 = expf(m1v - mn1);
        float s0 = 0.f, s1 = 0.f;
        #pragma unroll
        for (int j = 0; j < 8; ++j) {
            s[j][0] = expf(s[j][0] - mn0); s[j][1] = expf(s[j][1] - mn0);
            s[j][2] = expf(s[j][2] - mn1); s[j][3] = expf(s[j][3] - mn1);
            s0 += s[j][0] + s[j][1];
            s1 += s[j][2] + s[j][3];
        }
        s0 += __shfl_xor_sync(0xffffffffu, s0, 1); s0 += __shfl_xor_sync(0xffffffffu, s0, 2);
        s1 += __shfl_xor_sync(0xffffffffu, s1, 1); s1 += __shfl_xor_sync(0xffffffffu, s1, 2);
        l0v = l0v * al0 + s0; l1v = l1v * al1 + s1;
        m0v = mn0; m1v = mn1;
        #pragma unroll
        for (int j = 0; j < 8; ++j) {
            o[j][0] *= al0; o[j][1] *= al0; o[j][2] *= al1; o[j][3] *= al1;
        }
        #pragma unroll
        for (int j = 0; j < 8; ++j) {
            int ci = 4 * j + tig;
            __nv_bfloat16 p0 = __float2bfloat16_rn(s[j][0]), p1 = __float2bfloat16_rn(s[j][1]);
            __nv_bfloat16 p2 = __float2bfloat16_rn(s[j][2]), p3 = __float2bfloat16_rn(s[j][3]);
            PhU[rl0 * 36 + ci]       = packbf(bfl(p0), bfl(p1));
            PhU[(rl0 + 8) * 36 + ci] = packbf(bfl(p2), bfl(p3));
            PlU[rl0 * 36 + ci]       = packbf(s[j][0] - bfl(p0), s[j][1] - bfl(p1));
            PlU[(rl0 + 8) * 36 + ci] = packbf(s[j][2] - bfl(p2), s[j][3] - bfl(p3));
        }
        __syncwarp();
        #pragma unroll
        for (int ks = 0; ks < 4; ++ks) {
            int po = ks * 8;
            uint32_t pa[4], pla[4];
            pa[0]  = PhU[rl0 * 36 + po + tig];
            pa[1]  = PhU[(rl0 + 8) * 36 + po + tig];
            pa[2]  = PhU[rl0 * 36 + po + tig + 4];
            pa[3]  = PhU[(rl0 + 8) * 36 + po + tig + 4];
            pla[0] = PlU[rl0 * 36 + po + tig];
            pla[1] = PlU[(rl0 + 8) * 36 + po + tig];
            pla[2] = PlU[rl0 * 36 + po + tig + 4];
            pla[3] = PlU[(rl0 + 8) * 36 + po + tig + 4];
            #pragma unroll
            for (int j = 0; j < 8; ++j) {
                int n = 8 * j + grp;
                uint32_t vh0 = VhU[n * 36 + po + tig], vh1 = VhU[n * 36 + po + tig + 4];
                uint32_t vl0 = VlU[n * 36 + po + tig], vl1 = VlU[n * 36 + po + tig + 4];
                MMAB(o[j], pa, vh0, vh1);
                MMAB(o[j], pa, vl0, vl1);
                MMAB(o[j], pla, vh0, vh1);
            }
        }
        __syncthreads();
    }

    float i0 = 1.f / l0v, i1 = 1.f / l1v;
    size_t t0 = (size_t)(b * CS + qt * 128 + rl0);
    #pragma unroll
    for (int j = 0; j < 8; ++j) {
        int d = 8 * j + 2 * tig;
        size_t i0a = (t0 * CH + h) * CHD + d;
        size_t i1a = ((t0 + 8) * CH + h) * CHD + d;
        float v00 = o[j][0] * i0, v01 = o[j][1] * i0;
        float v10 = o[j][2] * i1, v11 = o[j][3] * i1;
        __nv_bfloat16 h00 = __float2bfloat16_rn(v00), h01 = __float2bfloat16_rn(v01);
        __nv_bfloat16 h10 = __float2bfloat16_rn(v10), h11 = __float2bfloat16_rn(v11);
        *(__nv_bfloat162*)&g_atthb[i0a] = __nv_bfloat162(h00, h01);
        *(__nv_bfloat162*)&g_attlb[i0a] = __nv_bfloat162(
            __float2bfloat16_rn(v00 - bfl(h00)), __float2bfloat16_rn(v01 - bfl(h01)));
        *(__nv_bfloat162*)&g_atthb[i1a] = __nv_bfloat162(h10, h11);
        *(__nv_bfloat162*)&g_attlb[i1a] = __nv_bfloat162(
            __float2bfloat16_rn(v10 - bfl(h10)), __float2bfloat16_rn(v11 - bfl(h11)));
    }
}

// ---------------- router ----------------
__global__ void router_kernel(const float* __restrict__ Gw, float* __restrict__ scores_out) {
    int gtid = blockIdx.x * blockDim.x + threadIdx.x;
    int warp = gtid >> 5, lane = threadIdx.x & 31;
    if (warp >= CT) return;
    const float* xr = g_hn + (size_t)warp * CD;
    float acc[CE] = {};
    for (int d = lane; d < CD; d += 32) {
        float xv = xr[d];
        const float* gr = Gw + (size_t)d * CE;
        #pragma unroll
        for (int e = 0; e < CE; ++e) acc[e] += xv * gr[e];
    }
    #pragma unroll
    for (int off = 16; off; off >>= 1)
        #pragma unroll
        for (int e = 0; e < CE; ++e) acc[e] += __shfl_down_sync(0xffffffffu, acc[e], off);
    if (lane == 0) {
        float mx = acc[0];
        #pragma unroll
        for (int e = 1; e < CE; ++e) mx = fmaxf(mx, acc[e]);
        float p[CE], sum = 0.f;
        #pragma unroll
        for (int e = 0; e < CE; ++e) { p[e] = expf(acc[e] - mx); sum += p[e]; }
        float inv = 1.f / sum;
        #pragma unroll
        for (int e = 0; e < CE; ++e) { p[e] *= inv; scores_out[(size_t)warp * CE + e] = p[e]; }
        int e0 = 0; float b0 = p[0];
        #pragma unroll
        for (int e = 1; e < CE; ++e) if (p[e] > b0) { b0 = p[e]; e0 = e; }
        int e1 = -1; float b1 = -1.f;
        #pragma unroll
        for (int e = 0; e < CE; ++e) if (e != e0 && p[e] > b1) { b1 = p[e]; e1 = e; }
        float wsum = b0 + b1;
        int p0 = atomicAdd(&g_cnt[e0], 1);
        g_tok[e0 * CT + p0] = warp; g_wsl[e0 * CT + p0] = b0 / wsum;
        g_slot[warp * 2 + 0] = e0 * CT + p0;
        int p1 = atomicAdd(&g_cnt[e1], 1);
        g_tok[e1 * CT + p1] = warp; g_wsl[e1 * CT + p1] = b1 / wsum;
        g_slot[warp * 2 + 1] = e1 * CT + p1;
    }
}

// ---------------- MoE up (bf16, permuted layout, dynamic smem) ----------------
constexpr size_t MOEUP_SMEM = (size_t)(2 * PMA + 4 * PMB) * 2;
__global__ __launch_bounds__(256, 2) void moe_up_bf16() {
    int e = blockIdx.z, cnt = g_cnt[e], r0 = blockIdx.y * 128;
    if (r0 >= cnt) return;
    int f0 = blockIdx.x * 64, tid = threadIdx.x;
    extern __shared__ __nv_bfloat16 msm[];
    __nv_bfloat16* sA  = msm;
    __nv_bfloat16* sB1 = sA + 2 * PMA;
    __nv_bfloat16* sB3 = sB1 + 2 * PMB;
    __shared__ int toks[128]; __shared__ float wrow[128];
    if (tid < 128) {
        int rr = r0 + tid; bool ok = rr < cnt;
        toks[tid] = ok ? g_tok[e * CT + rr] : g_tok[e * CT];
        wrow[tid] = ok ? g_wsl[e * CT + rr] : 0.f;
    }
    __syncthreads();
    const __nv_bfloat16* pA0 = g_hnb + (size_t)toks[tid >> 2] * CD + (tid & 3) * 8;
    const __nv_bfloat16* pA1 = g_hnb + (size_t)toks[(tid >> 2) + 64] * CD + (tid & 3) * 8;
    const __nv_bfloat16* pB1 = g_w1b + (size_t)e * CF * CD + (size_t)(f0 + (tid >> 2)) * CD + (tid & 3) * 8;
    const __nv_bfloat16* pB3 = g_w3b + (size_t)e * CF * CD + (size_t)(f0 + (tid >> 2)) * CD + (tid & 3) * 8;
    float c1[2][4][4] = {}, c3[2][4][4] = {};
    mma_core_bf16p<true>(pA0, pA1, pB1, pB3, CD, sA, sB1, sB3, tid, c1, c3);
    int lane = tid & 31, wid = tid >> 5, grp = lane >> 2, tig = lane & 3;
    int wm = (wid >> 1) * 32, wn = (wid & 1) * 32;
    #pragma unroll
    for (int i = 0; i < 2; ++i) {
        int rloc = wm + 16 * i + grp;
        float w0 = wrow[rloc], w1v = wrow[rloc + 8];
        size_t rr0 = (size_t)e * CT + r0 + rloc;
        #pragma unroll
        for (int j = 0; j < 4; ++j) {
            int cc = f0 + wn + 8 * j + 2 * tig;
            int P = cc >> 1, p8 = P & 7;
            int npos = (p8 < 4) ? (2 * p8) : (2 * (p8 - 4) + 1);
            int ncc = (((P & ~7) | npos) << 1);
            float x0 = c1[i][j][0], x1 = c1[i][j][1], x2 = c1[i][j][2], x3 = c1[i][j][3];
            float y0 = (x0 / (1.f + expf(-x0))) * c3[i][j][0] * w0;
            float y1 = (x1 / (1.f + expf(-x1))) * c3[i][j][1] * w0;
            float y2 = (x2 / (1.f + expf(-x2))) * c3[i][j][2] * w1v;
            float y3 = (x3 / (1.f + expf(-x3))) * c3[i][j][3] * w1v;
            *(__nv_bfloat162*)&g_hexpb[rr0 * CF + ncc]       = __floats2bfloat162_rn(y0, y1);
            *(__nv_bfloat162*)&g_hexpb[(rr0 + 8) * CF + ncc] = __floats2bfloat162_rn(y2, y3);
        }
    }
}

// ---------------- MoE down (bf16, permuted layout, dynamic smem) ----------------
constexpr size_t MOEDN_SMEM = (size_t)(2 * PMA + 2 * PMB) * 2;
__global__ __launch_bounds__(256, 2) void moe_down_bf16() {
    int e = blockIdx.z, cnt = g_cnt[e], r0 = blockIdx.y * 128;
    if (r0 >= cnt) return;
    int n0 = blockIdx.x * 64, tid = threadIdx.x;
    extern __shared__ __nv_bfloat16 msm[];
    __nv_bfloat16* sA = msm;
    __nv_bfloat16* sB = sA + 2 * PMA;
    const __nv_bfloat16* pA0 = g_hexpb + (size_t)(e * CT + r0 + (tid >> 2)) * CF + (tid & 3) * 8;
    const __nv_bfloat16* pA1 = pA0 + (size_t)64 * CF;
    const __nv_bfloat16* pB  = g_w2b + (size_t)e * CD * CF + (size_t)(n0 + (tid >> 2)) * CF + (tid & 3) * 8;
    float c1[2][4][4] = {};
    mma_core_bf16p<false>(pA0, pA1, pB, pB, CF, sA, sB, sB, tid, c1, c1);
    float* C = g_y + ((size_t)e * CT + r0) * CD;
    int lane = tid & 31, wid = tid >> 5, grp = lane >> 2, tig = lane & 3;
    int wm = (wid >> 1) * 32, wn = (wid & 1) * 32;
    #pragma unroll
    for (int i = 0; i < 2; ++i) {
        int rloc = wm + 16 * i + grp;
        #pragma unroll
        for (int j = 0; j < 4; ++j) {
            int cc = n0 + wn + 8 * j + 2 * tig;
            *(float2*)&C[(size_t)rloc * CD + cc]       = make_float2(c1[i][j][0], c1[i][j][1]);
            *(float2*)&C[(size_t)(rloc + 8) * CD + cc] = make_float2(c1[i][j][2], c1[i][j][3]);
        }
    }
}

// ---------------- combine ----------------
__global__ void combine_kernel(float* __restrict__ out) {
    int idx = blockIdx.x * 256 + threadIdx.x;
    if (idx >= CT * CD) return;
    int t = idx >> 10, d = idx & 1023;
    int s0 = g_slot[t * 2 + 0], s1 = g_slot[t * 2 + 1];
    out[idx] = g_h1[idx] + g_y[(size_t)s0 * CD + d] + g_y[(size_t)s1 * CD + d];
}

// ---------------- stream/event infrastructure ----------------
static cudaStream_t s_s1 = nullptr, s_s2 = nullptr;
static cudaEvent_t  s_evRoot = nullptr, s_ev1 = nullptr, s_ev2 = nullptr;
static struct StreamInit {
    StreamInit() {
        cudaFree(0);
        if (cudaStreamCreateWithFlags(&s_s1, cudaStreamNonBlocking) != cudaSuccess) s_s1 = nullptr;
        if (cudaStreamCreateWithFlags(&s_s2, cudaStreamNonBlocking) != cudaSuccess) s_s2 = nullptr;
        if (cudaEventCreateWithFlags(&s_evRoot, cudaEventDisableTiming) != cudaSuccess) s_evRoot = nullptr;
        if (cudaEventCreateWithFlags(&s_ev1, cudaEventDisableTiming) != cudaSuccess) s_ev1 = nullptr;
        if (cudaEventCreateWithFlags(&s_ev2, cudaEventDisableTiming) != cudaSuccess) s_ev2 = nullptr;
    }
} s_streamInit;

// ---------------- launcher ----------------
extern "C" void kernel_launch(void* const* d_in, const int* in_sizes, int n_in,
                              void* d_out, int out_size) {
    const float* hid = (const float*)d_in[0];
    const int*   pos = (const int*)  d_in[1];
    const float* ln1 = (const float*)d_in[3];
    const float* ln2 = (const float*)d_in[4];
    const float* wq  = (const float*)d_in[5];
    const float* wk  = (const float*)d_in[6];
    const float* wv  = (const float*)d_in[7];
    const float* wo  = (const float*)d_in[8];
    const float* gw  = (const float*)d_in[9];
    const float* w1  = (const float*)d_in[10];
    const float* w3  = (const float*)d_in[11];
    const float* w2  = (const float*)d_in[12];
    float* out        = (float*)d_out;
    float* out_scores = out + (size_t)CT * CD;

    __nv_bfloat16 *xnbh, *xnbl, *hnb, *w1b, *w3b, *w2b;
    __nv_bfloat16 *wqTh, *wqTl, *wkTh, *wkTl, *wvTh, *wvTl, *woTh, *woTl;
    cudaGetSymbolAddress((void**)&xnbh, g_xnbh);
    cudaGetSymbolAddress((void**)&xnbl, g_xnbl);
    cudaGetSymbolAddress((void**)&hnb, g_hnb);
    cudaGetSymbolAddress((void**)&w1b, g_w1b);
    cudaGetSymbolAddress((void**)&w3b, g_w3b);
    cudaGetSymbolAddress((void**)&w2b, g_w2b);
    cudaGetSymbolAddress((void**)&wqTh, g_wqTh); cudaGetSymbolAddress((void**)&wqTl, g_wqTl);
    cudaGetSymbolAddress((void**)&wkTh, g_wkTh); cudaGetSymbolAddress((void**)&wkTl, g_wkTl);
    cudaGetSymbolAddress((void**)&wvTh, g_wvTh); cudaGetSymbolAddress((void**)&wvTl, g_wvTl);
    cudaGetSymbolAddress((void**)&woTh, g_woTh); cudaGetSymbolAddress((void**)&woTl, g_woTl);
    float* h1; cudaGetSymbolAddress((void**)&h1, g_h1);
    float* hn; cudaGetSymbolAddress((void**)&hn, g_hn);
    int*  cnt; cudaGetSymbolAddress((void**)&cnt, g_cnt);

    cudaFuncSetAttribute(flash_bf16, cudaFuncAttributeMaxDynamicSharedMemorySize, FL_SMEM);
    cudaFuncSetAttribute(qkv_b3,   cudaFuncAttributeMaxDynamicSharedMemorySize, B3_SMEM);
    cudaFuncSetAttribute(oproj_b3, cudaFuncAttributeMaxDynamicSharedMemorySize, B3_SMEM);
    cudaFuncSetAttribute(moe_up_bf16,   cudaFuncAttributeMaxDynamicSharedMemorySize, MOEUP_SMEM);
    cudaFuncSetAttribute(moe_down_bf16, cudaFuncAttributeMaxDynamicSharedMemorySize, MOEDN_SMEM);

    bool par = s_s1 && s_s2 && s_evRoot && s_ev1 && s_ev2;

    if (par) {
        cudaEventRecord(s_evRoot, 0);
        cudaStreamWaitEvent(s_s1, s_evRoot, 0);
        cudaStreamWaitEvent(s_s2, s_evRoot, 0);

        // s1: small qkv/o weight splits — full grid, finish fast (gate qkv/oproj)
        transpose_w_split<<<dim3(32, 32), 256, 0, s_s1>>>(wq, wqTh, wqTl, CD, CD);
        transpose_w_split<<<dim3(8, 32),  256, 0, s_s1>>>(wk, wkTh, wkTl, CD, 256);
        transpose_w_split<<<dim3(8, 32),  256, 0, s_s1>>>(wv, wvTh, wvTl, CD, 256);
        transpose_w_split<<<dim3(32, 32), 256, 0, s_s1>>>(wo, woTh, woTl, CD, CD);
        cudaEventRecord(s_ev1, s_s1);

        // s2: big MoE transposes — small grid-stride so they sip SMs under attention
        transpose_w_gs<<<96, 256, 0, s_s2>>>(w1, w1b, CD, CF, CE);
        transpose_w_gs<<<96, 256, 0, s_s2>>>(w3, w3b, CD, CF, CE);
        transpose_w_gs<<<96, 256, 0, s_s2>>>(w2, w2b, CF, CD, CE);
        cudaEventRecord(s_ev2, s_s2);

        rmsnorm_split<<<CT, 256>>>(hid, ln1, xnbh, xnbl);
        cudaStreamWaitEvent(0, s_ev1, 0);
        qkv_b3<<<dim3(24, 16), 256, B3_SMEM>>>();
    } else {
        transpose_w_split<<<dim3(32, 32), 256>>>(wq, wqTh, wqTl, CD, CD);
        transpose_w_split<<<dim3(8, 32),  256>>>(wk, wkTh, wkTl, CD, 256);
        transpose_w_split<<<dim3(8, 32),  256>>>(wv, wvTh, wvTl, CD, 256);
        transpose_w_split<<<dim3(32, 32), 256>>>(wo, woTh, woTl, CD, CD);
        transpose_w_gs<<<148, 256>>>(w1, w1b, CD, CF, CE);
        transpose_w_gs<<<148, 256>>>(w3, w3b, CD, CF, CE);
        transpose_w_gs<<<148, 256>>>(w2, w2b, CF, CD, CE);
        rmsnorm_split<<<CT, 256>>>(hid, ln1, xnbh, xnbl);
        qkv_b3<<<dim3(24, 16), 256, B3_SMEM>>>();
    }

    {
        int total = CT * (CH + CKV) * 32;
        rope_kernel<<<(total + 255) / 256, 256>>>(pos);
    }
    flash_bf16<<<dim3(CB * CH, CS / 128), 256, FL_SMEM>>>();
    oproj_b3<<<dim3(16, 16), 256, B3_SMEM>>>(hid);
    rmsnorm_dual<<<CT, 256>>>(h1, ln2, hn, hnb);
    cudaMemsetAsync(cnt, 0, CE * sizeof(int));
    router_kernel<<<(CT * 32 + 255) / 256, 256>>>(gw, out_scores);

    if (par) cudaStreamWaitEvent(0, s_ev2, 0);

    moe_up_bf16<<<dim3(CF / 64, CT / 128, CE), 256, MOEUP_SMEM>>>();
    moe_down_bf16<<<dim3(CD / 64, CT / 128, CE), 256, MOEDN_SMEM>>>();
    combine_kernel<<<(CT * CD + 255) / 256, 256>>>(out);
}

// round 14
// speedup vs baseline: 1.4510x; 1.4510x over previous
#include <cuda_runtime.h>
#include <cuda_bf16.h>
#include <math.h>
#include <stdint.h>

constexpr int CB = 2, CS = 1024, CD = 1024;
constexpr int CH = 16, CKV = 4, CHD = 64;
constexpr int CE = 8, CF = 2048;
constexpr int CT = CB * CS;
constexpr float CEPS = 1e-6f;

__device__ __nv_bfloat16 g_xnbh[CT * CD], g_xnbl[CT * CD];
__device__ float g_q  [CT * CH  * CHD];
__device__ float g_k  [CT * CKV * CHD];
__device__ __nv_bfloat16 g_kbh[CT * CKV * CHD], g_kbl[CT * CKV * CHD];
__device__ __nv_bfloat16 g_vbTh[CB * CKV * CHD * CS], g_vbTl[CB * CKV * CHD * CS];
__device__ __nv_bfloat16 g_atthb[CT * CH * CHD], g_attlb[CT * CH * CHD];
__device__ float g_h1 [CT * CD];
__device__ float g_hn [CT * CD];
__device__ __nv_bfloat16 g_hnb[CT * CD];
__device__ int   g_cnt [CE];
__device__ int   g_tok [CE * CT];
__device__ float g_wsl [CE * CT];
__device__ int   g_slot[CT * 2];
__device__ __nv_bfloat16 g_hexpb[(size_t)CE * CT * CF];
__device__ float g_y   [(size_t)CE * CT * CD];
__device__ __nv_bfloat16 g_w1b[(size_t)CE * CF * CD];
__device__ __nv_bfloat16 g_w3b[(size_t)CE * CF * CD];
__device__ __nv_bfloat16 g_w2b[(size_t)CE * CD * CF];
__device__ __nv_bfloat16 g_wqTh[CD * CD],  g_wqTl[CD * CD];
__device__ __nv_bfloat16 g_wkTh[256 * CD], g_wkTl[256 * CD];
__device__ __nv_bfloat16 g_wvTh[256 * CD], g_wvTl[256 * CD];
__device__ __nv_bfloat16 g_woTh[CD * CD],  g_woTl[CD * CD];

#define U32(x) __float_as_uint(x)
#define MMAB(c, a, b0, b1) \
    asm volatile("mma.sync.aligned.m16n8k16.row.col.f32.bf16.bf16.f32 " \
        "{%0,%1,%2,%3}, {%4,%5,%6,%7}, {%8,%9}, {%0,%1,%2,%3};" \
        : "+f"((c)[0]), "+f"((c)[1]), "+f"((c)[2]), "+f"((c)[3]) \
        : "r"((a)[0]), "r"((a)[1]), "r"((a)[2]), "r"((a)[3]), "r"(b0), "r"(b1))

__device__ __forceinline__ void cpa16(uint32_t d, const void* s) {
    asm volatile("cp.async.ca.shared.global [%0], [%1], 16;" :: "r"(d), "l"(s));
}
#define CPC  asm volatile("cp.async.commit_group;")
#define CPW(n) asm volatile("cp.async.wait_group %0;" :: "n"(n))

__device__ __forceinline__ uint32_t packbf(float a, float b) {
    __nv_bfloat162 t = __floats2bfloat162_rn(a, b);
    return *(uint32_t*)&t;
}
__device__ __forceinline__ float bfl(__nv_bfloat16 h) { return __bfloat162float(h); }

// k-pair interleave permutation (within each 32-element block)
__device__ __forceinline__ int perm32(int d) {
    int pair = (d >> 1) & 15, e = d & 1;
    int p8 = pair & 7;
    int npos = (p8 < 4) ? (2 * p8) : (2 * (p8 - 4) + 1);
    int newpair = (pair & 8) | npos;
    return (d & ~31) | (newpair << 1) | e;
}

constexpr int MA_STG = 128 * 40;
constexpr int MB_STG = 64 * 40;
constexpr int PMA = 128 * 48;
constexpr int PMB = 64 * 48;

// ------------- bf16 permuted-layout core (MoE): LDS.64 fragments -------------
template<bool DUAL>
__device__ __forceinline__ void mma_core_bf16p(
    const __nv_bfloat16* pA0, const __nv_bfloat16* pA1,
    const __nv_bfloat16* pB1, const __nv_bfloat16* pB3,
    int K, __nv_bfloat16* sA, __nv_bfloat16* sB1, __nv_bfloat16* sB3, int tid,
    float c1[2][4][4], float c3[2][4][4])
{
    const int lane = tid & 31, wid = tid >> 5, grp = lane >> 2, tig = lane & 3;
    const int wm = (wid >> 1) * 32, wn = (wid & 1) * 32;
    uint32_t aA0 = (uint32_t)__cvta_generic_to_shared(sA) + (tid >> 2) * 96 + (tid & 3) * 16;
    uint32_t aA1 = aA0 + 64 * 96;
    uint32_t aB1 = (uint32_t)__cvta_generic_to_shared(sB1) + (tid >> 2) * 96 + (tid & 3) * 16;
    uint32_t aB3 = DUAL ? (uint32_t)__cvta_generic_to_shared(sB3) + (tid >> 2) * 96 + (tid & 3) * 16 : 0u;

    cpa16(aA0, pA0);
    cpa16(aA1, pA1);
    cpa16(aB1, pB1);
    if (DUAL) cpa16(aB3, pB3);
    CPC;

    int nt = K / 32;
    for (int t = 0; t < nt; ++t) {
        if (t + 1 < nt) {
            int k0 = (t + 1) * 32, st = (t + 1) & 1;
            cpa16(aA0 + st * (PMA * 2), pA0 + k0);
            cpa16(aA1 + st * (PMA * 2), pA1 + k0);
            cpa16(aB1 + st * (PMB * 2), pB1 + k0);
            if (DUAL) cpa16(aB3 + st * (PMB * 2), pB3 + k0);
            CPC; CPW(1);
        } else { CPW(0); }
        __syncthreads();
        const uint32_t* AU  = (const uint32_t*)(sA  + (t & 1) * PMA);
        const uint32_t* B1U = (const uint32_t*)(sB1 + (t & 1) * PMB);
        const uint32_t* B3U = (const uint32_t*)(sB3 + (t & 1) * PMB);
        #pragma unroll
        for (int ks = 0; ks < 2; ++ks) {
            int po = ks * 8 + 2 * tig;
            uint32_t a[2][4];
            #pragma unroll
            for (int i = 0; i < 2; ++i) {
                int r = wm + 16 * i + grp;
                uint2 t0 = *(const uint2*)&AU[r * 24 + po];
                uint2 t1 = *(const uint2*)&AU[(r + 8) * 24 + po];
                a[i][0] = t0.x; a[i][2] = t0.y;
                a[i][1] = t1.x; a[i][3] = t1.y;
            }
            #pragma unroll
            for (int j = 0; j < 4; ++j) {
                int n = wn + 8 * j + grp;
                uint2 b = *(const uint2*)&B1U[n * 24 + po];
                MMAB(c1[0][j], a[0], b.x, b.y);
                MMAB(c1[1][j], a[1], b.x, b.y);
                if (DUAL) {
                    uint2 d2 = *(const uint2*)&B3U[n * 24 + po];
                    MMAB(c3[0][j], a[0], d2.x, d2.y);
                    MMAB(c3[1][j], a[1], d2.x, d2.y);
                }
            }
        }
        __syncthreads();
    }
}

// ------------- bf16 3-term core (qkv/oproj) -------------
__device__ __forceinline__ void mma_core_bf16_3(
    const __nv_bfloat16* pAh0, const __nv_bfloat16* pAh1,
    const __nv_bfloat16* pAl0, const __nv_bfloat16* pAl1,
    const __nv_bfloat16* pBh, const __nv_bfloat16* pBl,
    int K, __nv_bfloat16* sm, int tid, float c[2][4][4])
{
    __nv_bfloat16* sAh = sm;
    __nv_bfloat16* sAl = sAh + 2 * MA_STG;
    __nv_bfloat16* sBh = sAl + 2 * MA_STG;
    __nv_bfloat16* sBl = sBh + 2 * MB_STG;
    const int lane = tid & 31, wid = tid >> 5, grp = lane >> 2, tig = lane & 3;
    const int wm = (wid >> 1) * 32, wn = (wid & 1) * 32;
    uint32_t off = (tid >> 2) * 80 + (tid & 3) * 16;
    uint32_t aAh0 = (uint32_t)__cvta_generic_to_shared(sAh) + off, aAh1 = aAh0 + 64 * 80;
    uint32_t aAl0 = (uint32_t)__cvta_generic_to_shared(sAl) + off, aAl1 = aAl0 + 64 * 80;
    uint32_t aBh  = (uint32_t)__cvta_generic_to_shared(sBh) + off;
    uint32_t aBl  = (uint32_t)__cvta_generic_to_shared(sBl) + off;

    cpa16(aAh0, pAh0); cpa16(aAh1, pAh1);
    cpa16(aAl0, pAl0); cpa16(aAl1, pAl1);
    cpa16(aBh, pBh);   cpa16(aBl, pBl);
    CPC;

    int nt = K / 32;
    for (int t = 0; t < nt; ++t) {
        if (t + 1 < nt) {
            int k0 = (t + 1) * 32, st = (t + 1) & 1;
            cpa16(aAh0 + st * (MA_STG * 2), pAh0 + k0);
            cpa16(aAh1 + st * (MA_STG * 2), pAh1 + k0);
            cpa16(aAl0 + st * (MA_STG * 2), pAl0 + k0);
            cpa16(aAl1 + st * (MA_STG * 2), pAl1 + k0);
            cpa16(aBh  + st * (MB_STG * 2), pBh + k0);
            cpa16(aBl  + st * (MB_STG * 2), pBl + k0);
            CPC; CPW(1);
        } else { CPW(0); }
        __syncthreads();
        const uint32_t* AhU = (const uint32_t*)(sAh + (t & 1) * MA_STG);
        const uint32_t* AlU = (const uint32_t*)(sAl + (t & 1) * MA_STG);
        const uint32_t* BhU = (const uint32_t*)(sBh + (t & 1) * MB_STG);
        const uint32_t* BlU = (const uint32_t*)(sBl + (t & 1) * MB_STG);
        #pragma unroll
        for (int ks = 0; ks < 2; ++ks) {
            int po = ks * 8;
            uint32_t ah[2][4], al[2][4];
            #pragma unroll
            for (int i = 0; i < 2; ++i) {
                int r = wm + 16 * i + grp;
                ah[i][0] = AhU[r * 20 + po + tig];
                ah[i][1] = AhU[(r + 8) * 20 + po + tig];
                ah[i][2] = AhU[r * 20 + po + tig + 4];
                ah[i][3] = AhU[(r + 8) * 20 + po + tig + 4];
                al[i][0] = AlU[r * 20 + po + tig];
                al[i][1] = AlU[(r + 8) * 20 + po + tig];
                al[i][2] = AlU[r * 20 + po + tig + 4];
                al[i][3] = AlU[(r + 8) * 20 + po + tig + 4];
            }
            #pragma unroll
            for (int j = 0; j < 4; ++j) {
                int n = wn + 8 * j + grp;
                uint32_t bh0 = BhU[n * 20 + po + tig], bh1 = BhU[n * 20 + po + tig + 4];
                uint32_t bl0 = BlU[n * 20 + po + tig], bl1 = BlU[n * 20 + po + tig + 4];
                #pragma unroll
                for (int i = 0; i < 2; ++i) {
                    MMAB(c[i][j], ah[i], bh0, bh1);
                    MMAB(c[i][j], ah[i], bl0, bl1);
                    MMAB(c[i][j], al[i], bh0, bh1);
                }
            }
        }
        __syncthreads();
    }
}

// ---------------- MoE weight transpose (k-permuted), full grid ----------------
__global__ void transpose_w(const float* __restrict__ src, __nv_bfloat16* __restrict__ dst,
                            int R, int C) {
    __shared__ float t[32][33];
    const float* s = src + (size_t)blockIdx.z * R * C;
    __nv_bfloat16* d = dst + (size_t)blockIdx.z * R * C;
    int r0 = blockIdx.y * 32, c0 = blockIdx.x * 32;
    int tx = threadIdx.x & 31, ty = threadIdx.x >> 5;
    #pragma unroll
    for (int i = 0; i < 4; ++i) {
        int r = ty + i * 8;
        t[r][tx] = s[(size_t)(r0 + r) * C + c0 + tx];
    }
    __syncthreads();
    int ptx = perm32(tx);
    #pragma unroll
    for (int i = 0; i < 4; ++i) {
        int r = ty + i * 8;
        d[(size_t)(c0 + r) * R + r0 + ptx] = __float2bfloat16_rn(t[tx][r]);
    }
}

// qkv/o weights: unpermuted hi/lo split
__global__ void transpose_w_split(const float* __restrict__ src,
                                  __nv_bfloat16* __restrict__ dh, __nv_bfloat16* __restrict__ dl,
                                  int R, int C) {
    __shared__ float t[32][33];
    int r0 = blockIdx.y * 32, c0 = blockIdx.x * 32;
    int tx = threadIdx.x & 31, ty = threadIdx.x >> 5;
    #pragma unroll
    for (int i = 0; i < 4; ++i) {
        int r = ty + i * 8;
        t[r][tx] = src[(size_t)(r0 + r) * C + c0 + tx];
    }
    __syncthreads();
    #pragma unroll
    for (int i = 0; i < 4; ++i) {
        int r = ty + i * 8;
        float v = t[tx][r];
        __nv_bfloat16 h = __float2bfloat16_rn(v);
        size_t idx = (size_t)(c0 + r) * R + r0 + tx;
        dh[idx] = h;
        dl[idx] = __float2bfloat16_rn(v - __bfloat162float(h));
    }
}

// ---------------- RMSNorm producing bf16 hi/lo ----------------
__global__ void rmsnorm_split(const float* __restrict__ x, const float* __restrict__ w,
                              __nv_bfloat16* __restrict__ oh, __nv_bfloat16* __restrict__ ol) {
    int t = blockIdx.x;
    const float* xr = x + (size_t)t * CD;
    float ss = 0.f;
    for (int d = threadIdx.x; d < CD; d += 256) { float v = xr[d]; ss += v * v; }
    __shared__ float red[256];
    red[threadIdx.x] = ss;
    __syncthreads();
    for (int s = 128; s > 0; s >>= 1) {
        if (threadIdx.x < s) red[threadIdx.x] += red[threadIdx.x + s];
        __syncthreads();
    }
    __shared__ float rinv;
    if (threadIdx.x == 0) rinv = rsqrtf(red[0] * (1.f / CD) + CEPS);
    __syncthreads();
    for (int d = threadIdx.x; d < CD; d += 256) {
        float v = xr[d] * rinv * w[d];
        size_t idx = (size_t)t * CD + d;
        __nv_bfloat16 h = __float2bfloat16_rn(v);
        oh[idx] = h;
        ol[idx] = __float2bfloat16_rn(v - __bfloat162float(h));
    }
}

// ---------------- RMSNorm dual: exact fp32 (router) + k-permuted bf16 (MoE A) ----------------
__global__ void rmsnorm_dual(const float* __restrict__ x, const float* __restrict__ w,
                             float* __restrict__ out, __nv_bfloat16* __restrict__ outb) {
    int t = blockIdx.x;
    const float* xr = x + (size_t)t * CD;
    float ss = 0.f;
    for (int d = threadIdx.x; d < CD; d += 256) { float v = xr[d]; ss += v * v; }
    __shared__ float red[256];
    red[threadIdx.x] = ss;
    __syncthreads();
    for (int s = 128; s > 0; s >>= 1) {
        if (threadIdx.x < s) red[threadIdx.x] += red[threadIdx.x + s];
        __syncthreads();
    }
    __shared__ float rinv;
    if (threadIdx.x == 0) rinv = rsqrtf(red[0] * (1.f / CD) + CEPS);
    __syncthreads();
    for (int d = threadIdx.x; d < CD; d += 256) {
        float v = xr[d] * rinv * w[d];
        out[(size_t)t * CD + d] = v;
        outb[(size_t)t * CD + perm32(d)] = __float2bfloat16_rn(v);
    }
}

// ---------------- fused QKV projection (3-term bf16); V written transposed bf16 hi/lo ----
constexpr size_t B3_SMEM = (size_t)(4 * MA_STG + 4 * MB_STG) * 2;
__global__ __launch_bounds__(256) void qkv_b3() {
    extern __shared__ __nv_bfloat16 bsm[];
    int n0 = blockIdx.x * 64, m0 = blockIdx.y * 128, tid = threadIdx.x;
    const __nv_bfloat16 *Bh, *Bl; float* C; int ldc, nc; bool isV = false;
    if (n0 < 1024)      { Bh = g_wqTh; Bl = g_wqTl; C = g_q; ldc = 1024; nc = n0; }
    else if (n0 < 1280) { Bh = g_wkTh; Bl = g_wkTl; C = g_k; ldc = 256;  nc = n0 - 1024; }
    else                { Bh = g_wvTh; Bl = g_wvTl; C = nullptr; ldc = 256; nc = n0 - 1280; isV = true; }
    const __nv_bfloat16* pAh0 = g_xnbh + (size_t)(m0 + (tid >> 2)) * CD + (tid & 3) * 8;
    const __nv_bfloat16* pAh1 = pAh0 + (size_t)64 * CD;
    const __nv_bfloat16* pAl0 = g_xnbl + (size_t)(m0 + (tid >> 2)) * CD + (tid & 3) * 8;
    const __nv_bfloat16* pAl1 = pAl0 + (size_t)64 * CD;
    const __nv_bfloat16* pBh  = Bh + (size_t)(nc + (tid >> 2)) * CD + (tid & 3) * 8;
    const __nv_bfloat16* pBl  = Bl + (size_t)(nc + (tid >> 2)) * CD + (tid & 3) * 8;
    float c[2][4][4] = {};
    mma_core_bf16_3(pAh0, pAh1, pAl0, pAl1, pBh, pBl, CD, bsm, tid, c);
    int lane = tid & 31, wid = tid >> 5, grp = lane >> 2, tig = lane & 3;
    int wm = (wid >> 1) * 32, wn = (wid & 1) * 32;
    if (!isV) {
        #pragma unroll
        for (int i = 0; i < 2; ++i) {
            int r = m0 + wm + 16 * i + grp;
            #pragma unroll
            for (int j = 0; j < 4; ++j) {
                int cc = nc + wn + 8 * j + 2 * tig;
                *(float2*)&C[(size_t)r * ldc + cc]       = make_float2(c[i][j][0], c[i][j][1]);
                *(float2*)&C[(size_t)(r + 8) * ldc + cc] = make_float2(c[i][j][2], c[i][j][3]);
            }
        }
    } else {
        #pragma unroll
        for (int i = 0; i < 2; ++i) {
            #pragma unroll
            for (int j = 0; j < 4; ++j) {
                int cc = nc + wn + 8 * j + 2 * tig;
                #pragma unroll
                for (int u = 0; u < 4; ++u) {
                    int r = m0 + wm + 16 * i + grp + (u >> 1) * 8;
                    int ccc = cc + (u & 1);
                    float v = c[i][j][u];
                    int bb = r >> 10, ss = r & 1023;
                    size_t o = ((size_t)(bb * CKV + (ccc >> 6)) * CHD + (ccc & 63)) * CS + ss;
                    __nv_bfloat16 hv = __float2bfloat16_rn(v);
                    g_vbTh[o] = hv;
                    g_vbTl[o] = __float2bfloat16_rn(v - bfl(hv));
                }
            }
        }
    }
}

// ---------------- O projection + residual (3-term bf16) ----------------
__global__ __launch_bounds__(256) void oproj_b3(const float* __restrict__ Res) {
    extern __shared__ __nv_bfloat16 bsm[];
    int n0 = blockIdx.x * 64, m0 = blockIdx.y * 128, tid = threadIdx.x;
    const __nv_bfloat16* pAh0 = g_atthb + (size_t)(m0 + (tid >> 2)) * CD + (tid & 3) * 8;
    const __nv_bfloat16* pAh1 = pAh0 + (size_t)64 * CD;
    const __nv_bfloat16* pAl0 = g_attlb + (size_t)(m0 + (tid >> 2)) * CD + (tid & 3) * 8;
    const __nv_bfloat16* pAl1 = pAl0 + (size_t)64 * CD;
    const __nv_bfloat16* pBh  = g_woTh + (size_t)(n0 + (tid >> 2)) * CD + (tid & 3) * 8;
    const __nv_bfloat16* pBl  = g_woTl + (size_t)(n0 + (tid >> 2)) * CD + (tid & 3) * 8;
    float c[2][4][4] = {};
    mma_core_bf16_3(pAh0, pAh1, pAl0, pAl1, pBh, pBl, CD, bsm, tid, c);
    int lane = tid & 31, wid = tid >> 5, grp = lane >> 2, tig = lane & 3;
    int wm = (wid >> 1) * 32, wn = (wid & 1) * 32;
    #pragma unroll
    for (int i = 0; i < 2; ++i) {
        int r = m0 + wm + 16 * i + grp;
        #pragma unroll
        for (int j = 0; j < 4; ++j) {
            int cc = n0 + wn + 8 * j + 2 * tig;
            size_t i0 = (size_t)r * CD + cc, i1 = (size_t)(r + 8) * CD + cc;
            float2 r0 = *(const float2*)&Res[i0], r1 = *(const float2*)&Res[i1];
            *(float2*)&g_h1[i0] = make_float2(c[i][j][0] + r0.x, c[i][j][1] + r0.y);
            *(float2*)&g_h1[i1] = make_float2(c[i][j][2] + r1.x, c[i][j][3] + r1.y);
        }
    }
}

// ---------------- RoPE: q in-place fp32; k -> bf16 hi/lo ----------------
__global__ void rope_kernel(const int* __restrict__ pos_ids) {
    int idx = blockIdx.x * 256 + threadIdx.x;
    const int nq = CT * CH * 32, nk = CT * CKV * 32;
    if (idx >= nq + nk) return;
    if (idx < nq) {
        int i = idx & 31; int th = idx >> 5; int h = th % CH; int t = th / CH;
        float* base = g_q + ((size_t)t * CH + h) * CHD;
        float p = (float)pos_ids[t];
        float freq = expf(-(2.f * i / (float)CHD) * logf(10000.f));
        float ang = p * freq, cv = cosf(ang), sv = sinf(ang);
        float x0 = base[i], x1 = base[i + 32];
        base[i] = x0 * cv - x1 * sv;
        base[i + 32] = x1 * cv + x0 * sv;
    } else {
        int id2 = idx - nq;
        int i = id2 & 31; int th = id2 >> 5; int h = th % CKV; int t = th / CKV;
        size_t boff = ((size_t)t * CKV + h) * CHD;
        const float* base = g_k + boff;
        float p = (float)pos_ids[t];
        float freq = expf(-(2.f * i / (float)CHD) * logf(10000.f));
        float ang = p * freq, cv = cosf(ang), sv = sinf(ang);
        float x0 = base[i], x1 = base[i + 32];
        float y0 = x0 * cv - x1 * sv;
        float y1 = x1 * cv + x0 * sv;
        __nv_bfloat16 h0 = __float2bfloat16_rn(y0), h1 = __float2bfloat16_rn(y1);
        g_kbh[boff + i]      = h0;
        g_kbl[boff + i]      = __float2bfloat16_rn(y0 - bfl(h0));
        g_kbh[boff + i + 32] = h1;
        g_kbl[boff + i + 32] = __float2bfloat16_rn(y1 - bfl(h1));
    }
}

// ---------------- flash attention (cp.async double-buffered K/V) ----------------
constexpr int FL_STG = 64 * 72;
constexpr int FL_SMEM = 128 * 72 * 4 + 8 * FL_STG * 2;
__global__ __launch_bounds__(256) void flash_bf16() {
    extern __shared__ char fsm[];
    float* Qs = (float*)fsm;
    uint32_t* PhU = (uint32_t*)fsm;
    uint32_t* PlU = PhU + 128 * 36;
    __nv_bfloat16* Kh = (__nv_bfloat16*)(fsm + 128 * 72 * 4);
    __nv_bfloat16* Kl = Kh + 2 * FL_STG;
    __nv_bfloat16* Vh = Kl + 2 * FL_STG;
    __nv_bfloat16* Vl = Vh + 2 * FL_STG;

    int bh = blockIdx.x, qt = 7 - blockIdx.y;
    int b = bh >> 4, h = bh & 15, kvh = h >> 2;
    int tid = threadIdx.x, lane = tid & 31, warp = tid >> 5, grp = lane >> 2, tig = lane & 3;
    int rl0 = warp * 16 + grp;

    uint32_t aKh = (uint32_t)__cvta_generic_to_shared(Kh);
    uint32_t aKl = (uint32_t)__cvta_generic_to_shared(Kl);
    uint32_t aVh = (uint32_t)__cvta_generic_to_shared(Vh);
    uint32_t aVl = (uint32_t)__cvta_generic_to_shared(Vl);

    auto load_tile = [&](int kt, int st) {
        uint32_t so = st * (FL_STG * 2);
        #pragma unroll
        for (int it = 0; it < 2; ++it) {
            int idx = tid + it * 256;
            int n = idx >> 3, c8 = (idx & 7) * 8;
            uint32_t dsto = so + (uint32_t)(n * 144 + c8 * 2);
            size_t gk = ((size_t)(b * CS + kt * 64 + n) * CKV + kvh) * CHD + c8;
            size_t gv = ((size_t)(b * CKV + kvh) * CHD + n) * CS + kt * 64 + c8;
            cpa16(aKh + dsto, g_kbh + gk);
            cpa16(aKl + dsto, g_kbl + gk);
            cpa16(aVh + dsto, g_vbTh + gv);
            cpa16(aVl + dsto, g_vbTl + gv);
        }
    };

    #pragma unroll
    for (int it = 0; it < 8; ++it) {
        int idx = tid + it * 256;
        int r = idx >> 4, d4 = (idx & 15) * 4;
        float4 qv = *(const float4*)&g_q[((size_t)(b * CS + qt * 128 + r) * CH + h) * CHD + d4];
        Qs[r * 72 + d4]     = qv.x * 0.125f;
        Qs[r * 72 + d4 + 1] = qv.y * 0.125f;
        Qs[r * 72 + d4 + 2] = qv.z * 0.125f;
        Qs[r * 72 + d4 + 3] = qv.w * 0.125f;
    }
    load_tile(0, 0);
    CPC;
    __syncthreads();

    uint32_t qh[4][4], ql[4][4];
    #pragma unroll
    for (int ks = 0; ks < 4; ++ks)
        #pragma unroll
        for (int u = 0; u < 4; ++u) {
            int kk = ks * 16 + 2 * (tig + (u >> 1) * 4);
            int rr = rl0 + (u & 1) * 8;
            float x0 = Qs[rr * 72 + kk], x1 = Qs[rr * 72 + kk + 1];
            __nv_bfloat16 h0 = __float2bfloat16_rn(x0), h1 = __float2bfloat16_rn(x1);
            qh[ks][u] = packbf(bfl(h0), bfl(h1));
            ql[ks][u] = packbf(x0 - bfl(h0), x1 - bfl(h1));
        }

    float o[8][4] = {};
    float m0v = -INFINITY, m1v = -INFINITY, l0v = 0.f, l1v = 0.f;
    int ntiles = 2 * (qt + 1);

    for (int kt = 0; kt < ntiles; ++kt) {
        if (kt + 1 < ntiles) {
            load_tile(kt + 1, (kt + 1) & 1);
            CPC; CPW(1);
        } else { CPW(0); }
        __syncthreads();
        const uint32_t* KhU = (const uint32_t*)(Kh + (kt & 1) * FL_STG);
        const uint32_t* KlU = (const uint32_t*)(Kl + (kt & 1) * FL_STG);
        const uint32_t* VhU = (const uint32_t*)(Vh + (kt & 1) * FL_STG);
        const uint32_t* VlU = (const uint32_t*)(Vl + (kt & 1) * FL_STG);

        float s[8][4] = {};
        #pragma unroll
        for (int ks = 0; ks < 4; ++ks) {
            int po = ks * 8;
            #pragma unroll
            for (int j = 0; j < 8; ++j) {
                int n = 8 * j + grp;
                uint32_t bh0 = KhU[n * 36 + po + tig], bh1 = KhU[n * 36 + po + tig + 4];
                uint32_t bl0 = KlU[n * 36 + po + tig], bl1 = KlU[n * 36 + po + tig + 4];
                MMAB(s[j], qh[ks], bh0, bh1);
                MMAB(s[j], qh[ks], bl0, bl1);
                MMAB(s[j], ql[ks], bh0, bh1);
            }
        }
        if (kt >= 2 * qt) {
            int rg0 = qt * 128 + rl0;
            #pragma unroll
            for (int j = 0; j < 8; ++j) {
                int cg = kt * 64 + 8 * j + 2 * tig;
                if (cg     > rg0)     s[j][0] = -INFINITY;
                if (cg + 1 > rg0)     s[j][1] = -INFINITY;
                if (cg     > rg0 + 8) s[j][2] = -INFINITY;
                if (cg + 1 > rg0 + 8) s[j][3] = -INFINITY;
            }
        }
        float mx0 = -INFINITY, mx1 = -INFINITY;
        #pragma unroll
        for (int j = 0; j < 8; ++j) {
            mx0 = fmaxf(mx0, fmaxf(s[j][0], s[j][1]));
            mx1 = fmaxf(mx1, fmaxf(s[j][2], s[j][3]));
        }
        mx0 = fmaxf(mx0, __shfl_xor_sync(0xffffffffu, mx0, 1));
        mx0 = fmaxf(mx0, __shfl_xor_sync(0xffffffffu, mx0, 2));
        mx1 = fmaxf(mx1, __shfl_xor_sync(0xffffffffu, mx1, 1));
        mx1 = fmaxf(mx1, __shfl_xor_sync(0xffffffffu, mx1, 2));
        float mn0 = fmaxf(m0v, mx0), mn1 = fmaxf(m1v, mx1);
        float al0 = expf(m0v - mn0), al1 = expf(m1v - mn1);
        float s0 = 0.f, s1 = 0.f;
        #pragma unroll
        for (int j = 0; j < 8; ++j) {
            s[j][0] = expf(s[j][0] - mn0); s[j][1] = expf(s[j][1] - mn0);
            s[j][2] = expf(s[j][2] - mn1); s[j][3] = expf(s[j][3] - mn1);
            s0 += s[j][0] + s[j][1];
            s1 += s[j][2] + s[j][3];
        }
        s0 += __shfl_xor_sync(0xffffffffu, s0, 1); s0 += __shfl_xor_sync(0xffffffffu, s0, 2);
        s1 += __shfl_xor_sync(0xffffffffu, s1, 1); s1 += __shfl_xor_sync(0xffffffffu, s1, 2);
        l0v = l0v * al0 + s0; l1v = l1v * al1 + s1;
        m0v = mn0; m1v = mn1;
        #pragma unroll
        for (int j = 0; j < 8; ++j) {
            o[j][0] *= al0; o[j][1] *= al0; o[j][2] *= al1; o[j][3] *= al1;
        }
        #pragma unroll
        for (int j = 0; j < 8; ++j) {
            int ci = 4 * j + tig;
            __nv_bfloat16 p0 = __float2bfloat16_rn(s[j][0]), p1 = __float2bfloat16_rn(s[j][1]);
            __nv_bfloat16 p2 = __float2bfloat16_rn(s[j][2]), p3 = __float2bfloat16_rn(s[j][3]);
            PhU[rl0 * 36 + ci]       = packbf(bfl(p0), bfl(p1));
            PhU[(rl0 + 8) * 36 + ci] = packbf(bfl(p2), bfl(p3));
            PlU[rl0 * 36 + ci]       = packbf(s[j][0] - bfl(p0), s[j][1] - bfl(p1));
            PlU[(rl0 + 8) * 36 + ci] = packbf(s[j][2] - bfl(p2), s[j][3] - bfl(p3));
        }
        __syncwarp();
        #pragma unroll
        for (int ks = 0; ks < 4; ++ks) {
            int po = ks * 8;
            uint32_t pa[4], pla[4];
            pa[0]  = PhU[rl0 * 36 + po + tig];
            pa[1]  = PhU[(rl0 + 8) * 36 + po + tig];
            pa[2]  = PhU[rl0 * 36 + po + tig + 4];
            pa[3]  = PhU[(rl0 + 8) * 36 + po + tig + 4];
            pla[0] = PlU[rl0 * 36 + po + tig];
            pla[1] = PlU[(rl0 + 8) * 36 + po + tig];
            pla[2] = PlU[rl0 * 36 + po + tig + 4];
            pla[3] = PlU[(rl0 + 8) * 36 + po + tig + 4];
            #pragma unroll
            for (int j = 0; j < 8; ++j) {
                int n = 8 * j + grp;
                uint32_t vh0 = VhU[n * 36 + po + tig], vh1 = VhU[n * 36 + po + tig + 4];
                uint32_t vl0 = VlU[n * 36 + po + tig], vl1 = VlU[n * 36 + po + tig + 4];
                MMAB(o[j], pa, vh0, vh1);
                MMAB(o[j], pa, vl0, vl1);
                MMAB(o[j], pla, vh0, vh1);
            }
        }
        __syncthreads();
    }

    float i0 = 1.f / l0v, i1 = 1.f / l1v;
    size_t t0 = (size_t)(b * CS + qt * 128 + rl0);
    #pragma unroll
    for (int j = 0; j < 8; ++j) {
        int d = 8 * j + 2 * tig;
        size_t i0a = (t0 * CH + h) * CHD + d;
        size_t i1a = ((t0 + 8) * CH + h) * CHD + d;
        float v00 = o[j][0] * i0, v01 = o[j][1] * i0;
        float v10 = o[j][2] * i1, v11 = o[j][3] * i1;
        __nv_bfloat16 h00 = __float2bfloat16_rn(v00), h01 = __float2bfloat16_rn(v01);
        __nv_bfloat16 h10 = __float2bfloat16_rn(v10), h11 = __float2bfloat16_rn(v11);
        *(__nv_bfloat162*)&g_atthb[i0a] = __nv_bfloat162(h00, h01);
        *(__nv_bfloat162*)&g_attlb[i0a] = __nv_bfloat162(
            __float2bfloat16_rn(v00 - bfl(h00)), __float2bfloat16_rn(v01 - bfl(h01)));
        *(__nv_bfloat162*)&g_atthb[i1a] = __nv_bfloat162(h10, h11);
        *(__nv_bfloat162*)&g_attlb[i1a] = __nv_bfloat162(
            __float2bfloat16_rn(v10 - bfl(h10)), __float2bfloat16_rn(v11 - bfl(h11)));
    }
}

// ---------------- router ----------------
__global__ void router_kernel(const float* __restrict__ Gw, float* __restrict__ scores_out) {
    int gtid = blockIdx.x * blockDim.x + threadIdx.x;
    int warp = gtid >> 5, lane = threadIdx.x & 31;
    if (warp >= CT) return;
    const float* xr = g_hn + (size_t)warp * CD;
    float acc[CE] = {};
    for (int d = lane; d < CD; d += 32) {
        float xv = xr[d];
        const float* gr = Gw + (size_t)d * CE;
        #pragma unroll
        for (int e = 0; e < CE; ++e) acc[e] += xv * gr[e];
    }
    #pragma unroll
    for (int off = 16; off; off >>= 1)
        #pragma unroll
        for (int e = 0; e < CE; ++e) acc[e] += __shfl_down_sync(0xffffffffu, acc[e], off);
    if (lane == 0) {
        float mx = acc[0];
        #pragma unroll
        for (int e = 1; e < CE; ++e) mx = fmaxf(mx, acc[e]);
        float p[CE], sum = 0.f;
        #pragma unroll
        for (int e = 0; e < CE; ++e) { p[e] = expf(acc[e] - mx); sum += p[e]; }
        float inv = 1.f / sum;
        #pragma unroll
        for (int e = 0; e < CE; ++e) { p[e] *= inv; scores_out[(size_t)warp * CE + e] = p[e]; }
        int e0 = 0; float b0 = p[0];
        #pragma unroll
        for (int e = 1; e < CE; ++e) if (p[e] > b0) { b0 = p[e]; e0 = e; }
        int e1 = -1; float b1 = -1.f;
        #pragma unroll
        for (int e = 0; e < CE; ++e) if (e != e0 && p[e] > b1) { b1 = p[e]; e1 = e; }
        float wsum = b0 + b1;
        int p0 = atomicAdd(&g_cnt[e0], 1);
        g_tok[e0 * CT + p0] = warp; g_wsl[e0 * CT + p0] = b0 / wsum;
        g_slot[warp * 2 + 0] = e0 * CT + p0;
        int p1 = atomicAdd(&g_cnt[e1], 1);
        g_tok[e1 * CT + p1] = warp; g_wsl[e1 * CT + p1] = b1 / wsum;
        g_slot[warp * 2 + 1] = e1 * CT + p1;
    }
}

// ---------------- MoE up (bf16, permuted layout, dynamic smem) ----------------
constexpr size_t MOEUP_SMEM = (size_t)(2 * PMA + 4 * PMB) * 2;
__global__ __launch_bounds__(256, 2) void moe_up_bf16() {
    int e = blockIdx.z, cnt = g_cnt[e], r0 = blockIdx.y * 128;
    if (r0 >= cnt) return;
    int f0 = blockIdx.x * 64, tid = threadIdx.x;
    extern __shared__ __nv_bfloat16 msm[];
    __nv_bfloat16* sA  = msm;
    __nv_bfloat16* sB1 = sA + 2 * PMA;
    __nv_bfloat16* sB3 = sB1 + 2 * PMB;
    __shared__ int toks[128]; __shared__ float wrow[128];
    if (tid < 128) {
        int rr = r0 + tid; bool ok = rr < cnt;
        toks[tid] = ok ? g_tok[e * CT + rr] : g_tok[e * CT];
        wrow[tid] = ok ? g_wsl[e * CT + rr] : 0.f;
    }
    __syncthreads();
    const __nv_bfloat16* pA0 = g_hnb + (size_t)toks[tid >> 2] * CD + (tid & 3) * 8;
    const __nv_bfloat16* pA1 = g_hnb + (size_t)toks[(tid >> 2) + 64] * CD + (tid & 3) * 8;
    const __nv_bfloat16* pB1 = g_w1b + (size_t)e * CF * CD + (size_t)(f0 + (tid >> 2)) * CD + (tid & 3) * 8;
    const __nv_bfloat16* pB3 = g_w3b + (size_t)e * CF * CD + (size_t)(f0 + (tid >> 2)) * CD + (tid & 3) * 8;
    float c1[2][4][4] = {}, c3[2][4][4] = {};
    mma_core_bf16p<true>(pA0, pA1, pB1, pB3, CD, sA, sB1, sB3, tid, c1, c3);
    int lane = tid & 31, wid = tid >> 5, grp = lane >> 2, tig = lane & 3;
    int wm = (wid >> 1) * 32, wn = (wid & 1) * 32;
    #pragma unroll
    for (int i = 0; i < 2; ++i) {
        int rloc = wm + 16 * i + grp;
        float w0 = wrow[rloc], w1v = wrow[rloc + 8];
        size_t rr0 = (size_t)e * CT + r0 + rloc;
        #pragma unroll
        for (int j = 0; j < 4; ++j) {
            int cc = f0 + wn + 8 * j + 2 * tig;
            int P = cc >> 1, p8 = P & 7;
            int npos = (p8 < 4) ? (2 * p8) : (2 * (p8 - 4) + 1);
            int ncc = (((P & ~7) | npos) << 1);
            float x0 = c1[i][j][0], x1 = c1[i][j][1], x2 = c1[i][j][2], x3 = c1[i][j][3];
            float y0 = (x0 / (1.f + expf(-x0))) * c3[i][j][0] * w0;
            float y1 = (x1 / (1.f + expf(-x1))) * c3[i][j][1] * w0;
            float y2 = (x2 / (1.f + expf(-x2))) * c3[i][j][2] * w1v;
            float y3 = (x3 / (1.f + expf(-x3))) * c3[i][j][3] * w1v;
            *(__nv_bfloat162*)&g_hexpb[rr0 * CF + ncc]       = __floats2bfloat162_rn(y0, y1);
            *(__nv_bfloat162*)&g_hexpb[(rr0 + 8) * CF + ncc] = __floats2bfloat162_rn(y2, y3);
        }
    }
}

// ---------------- MoE down (bf16, permuted layout, dynamic smem) ----------------
constexpr size_t MOEDN_SMEM = (size_t)(2 * PMA + 2 * PMB) * 2;
__global__ __launch_bounds__(256, 2) void moe_down_bf16() {
    int e = blockIdx.z, cnt = g_cnt[e], r0 = blockIdx.y * 128;
    if (r0 >= cnt) return;
    int n0 = blockIdx.x * 64, tid = threadIdx.x;
    extern __shared__ __nv_bfloat16 msm[];
    __nv_bfloat16* sA = msm;
    __nv_bfloat16* sB = sA + 2 * PMA;
    const __nv_bfloat16* pA0 = g_hexpb + (size_t)(e * CT + r0 + (tid >> 2)) * CF + (tid & 3) * 8;
    const __nv_bfloat16* pA1 = pA0 + (size_t)64 * CF;
    const __nv_bfloat16* pB  = g_w2b + (size_t)e * CD * CF + (size_t)(n0 + (tid >> 2)) * CF + (tid & 3) * 8;
    float c1[2][4][4] = {};
    mma_core_bf16p<false>(pA0, pA1, pB, pB, CF, sA, sB, sB, tid, c1, c1);
    float* C = g_y + ((size_t)e * CT + r0) * CD;
    int lane = tid & 31, wid = tid >> 5, grp = lane >> 2, tig = lane & 3;
    int wm = (wid >> 1) * 32, wn = (wid & 1) * 32;
    #pragma unroll
    for (int i = 0; i < 2; ++i) {
        int rloc = wm + 16 * i + grp;
        #pragma unroll
        for (int j = 0; j < 4; ++j) {
            int cc = n0 + wn + 8 * j + 2 * tig;
            *(float2*)&C[(size_t)rloc * CD + cc]       = make_float2(c1[i][j][0], c1[i][j][1]);
            *(float2*)&C[(size_t)(rloc + 8) * CD + cc] = make_float2(c1[i][j][2], c1[i][j][3]);
        }
    }
}

// ---------------- combine (float4 vectorized) ----------------
__global__ void combine_kernel(float* __restrict__ out) {
    int idx = blockIdx.x * 256 + threadIdx.x;
    if (idx >= CT * CD / 4) return;
    int e4 = idx * 4;
    int t = e4 >> 10, d = e4 & 1023;
    int s0 = g_slot[t * 2 + 0], s1 = g_slot[t * 2 + 1];
    float4 a = *(const float4*)&g_h1[e4];
    float4 y0 = *(const float4*)&g_y[(size_t)s0 * CD + d];
    float4 y1 = *(const float4*)&g_y[(size_t)s1 * CD + d];
    float4 r;
    r.x = a.x + y0.x + y1.x;
    r.y = a.y + y0.y + y1.y;
    r.z = a.z + y0.z + y1.z;
    r.w = a.w + y0.w + y1.w;
    *(float4*)&out[e4] = r;
}

// ---------------- stream/event infrastructure ----------------
static cudaStream_t s_s1 = nullptr, s_s2 = nullptr;
static cudaEvent_t  s_evRoot = nullptr, s_ev1 = nullptr, s_ev2 = nullptr;
static struct StreamInit {
    StreamInit() {
        cudaFree(0);
        if (cudaStreamCreateWithFlags(&s_s1, cudaStreamNonBlocking) != cudaSuccess) s_s1 = nullptr;
        if (cudaStreamCreateWithFlags(&s_s2, cudaStreamNonBlocking) != cudaSuccess) s_s2 = nullptr;
        if (cudaEventCreateWithFlags(&s_evRoot, cudaEventDisableTiming) != cudaSuccess) s_evRoot = nullptr;
        if (cudaEventCreateWithFlags(&s_ev1, cudaEventDisableTiming) != cudaSuccess) s_ev1 = nullptr;
        if (cudaEventCreateWithFlags(&s_ev2, cudaEventDisableTiming) != cudaSuccess) s_ev2 = nullptr;
    }
} s_streamInit;

// ---------------- launcher ----------------
extern "C" void kernel_launch(void* const* d_in, const int* in_sizes, int n_in,
                              void* d_out, int out_size) {
    const float* hid = (const float*)d_in[0];
    const int*   pos = (const int*)  d_in[1];
    const float* ln1 = (const float*)d_in[3];
    const float* ln2 = (const float*)d_in[4];
    const float* wq  = (const float*)d_in[5];
    const float* wk  = (const float*)d_in[6];
    const float* wv  = (const float*)d_in[7];
    const float* wo  = (const float*)d_in[8];
    const float* gw  = (const float*)d_in[9];
    const float* w1  = (const float*)d_in[10];
    const float* w3  = (const float*)d_in[11];
    const float* w2  = (const float*)d_in[12];
    float* out        = (float*)d_out;
    float* out_scores = out + (size_t)CT * CD;

    __nv_bfloat16 *xnbh, *xnbl, *hnb, *w1b, *w3b, *w2b;
    __nv_bfloat16 *wqTh, *wqTl, *wkTh, *wkTl, *wvTh, *wvTl, *woTh, *woTl;
    cudaGetSymbolAddress((void**)&xnbh, g_xnbh);
    cudaGetSymbolAddress((void**)&xnbl, g_xnbl);
    cudaGetSymbolAddress((void**)&hnb, g_hnb);
    cudaGetSymbolAddress((void**)&w1b, g_w1b);
    cudaGetSymbolAddress((void**)&w3b, g_w3b);
    cudaGetSymbolAddress((void**)&w2b, g_w2b);
    cudaGetSymbolAddress((void**)&wqTh, g_wqTh); cudaGetSymbolAddress((void**)&wqTl, g_wqTl);
    cudaGetSymbolAddress((void**)&wkTh, g_wkTh); cudaGetSymbolAddress((void**)&wkTl, g_wkTl);
    cudaGetSymbolAddress((void**)&wvTh, g_wvTh); cudaGetSymbolAddress((void**)&wvTl, g_wvTl);
    cudaGetSymbolAddress((void**)&woTh, g_woTh); cudaGetSymbolAddress((void**)&woTl, g_woTl);
    float* h1; cudaGetSymbolAddress((void**)&h1, g_h1);
    float* hn; cudaGetSymbolAddress((void**)&hn, g_hn);
    int*  cnt; cudaGetSymbolAddress((void**)&cnt, g_cnt);

    cudaFuncSetAttribute(flash_bf16, cudaFuncAttributeMaxDynamicSharedMemorySize, FL_SMEM);
    cudaFuncSetAttribute(qkv_b3,   cudaFuncAttributeMaxDynamicSharedMemorySize, B3_SMEM);
    cudaFuncSetAttribute(oproj_b3, cudaFuncAttributeMaxDynamicSharedMemorySize, B3_SMEM);
    cudaFuncSetAttribute(moe_up_bf16,   cudaFuncAttributeMaxDynamicSharedMemorySize, MOEUP_SMEM);
    cudaFuncSetAttribute(moe_down_bf16, cudaFuncAttributeMaxDynamicSharedMemorySize, MOEDN_SMEM);

    bool par = s_s1 && s_s2 && s_evRoot && s_ev1 && s_ev2;

    if (par) {
        cudaEventRecord(s_evRoot, 0);
        cudaStreamWaitEvent(s_s1, s_evRoot, 0);
        cudaStreamWaitEvent(s_s2, s_evRoot, 0);

        transpose_w_split<<<dim3(32, 32), 256, 0, s_s1>>>(wq, wqTh, wqTl, CD, CD);
        transpose_w_split<<<dim3(8, 32),  256, 0, s_s1>>>(wk, wkTh, wkTl, CD, 256);
        transpose_w_split<<<dim3(8, 32),  256, 0, s_s1>>>(wv, wvTh, wvTl, CD, 256);
        transpose_w_split<<<dim3(32, 32), 256, 0, s_s1>>>(wo, woTh, woTl, CD, CD);
        cudaEventRecord(s_ev1, s_s1);

        transpose_w<<<dim3(CF / 32, CD / 32, CE), 256, 0, s_s2>>>(w1, w1b, CD, CF);
        transpose_w<<<dim3(CF / 32, CD / 32, CE), 256, 0, s_s2>>>(w3, w3b, CD, CF);
        transpose_w<<<dim3(CD / 32, CF / 32, CE), 256, 0, s_s2>>>(w2, w2b, CF, CD);
        cudaEventRecord(s_ev2, s_s2);

        rmsnorm_split<<<CT, 256>>>(hid, ln1, xnbh, xnbl);
        cudaStreamWaitEvent(0, s_ev1, 0);
        qkv_b3<<<dim3(24, 16), 256, B3_SMEM>>>();
    } else {
        transpose_w_split<<<dim3(32, 32), 256>>>(wq, wqTh, wqTl, CD, CD);
        transpose_w_split<<<dim3(8, 32),  256>>>(wk, wkTh, wkTl, CD, 256);
        transpose_w_split<<<dim3(8, 32),  256>>>(wv, wvTh, wvTl, CD, 256);
        transpose_w_split<<<dim3(32, 32), 256>>>(wo, woTh, woTl, CD, CD);
        transpose_w<<<dim3(CF / 32, CD / 32, CE), 256>>>(w1, w1b, CD, CF);
        transpose_w<<<dim3(CF / 32, CD / 32, CE), 256>>>(w3, w3b, CD, CF);
        transpose_w<<<dim3(CD / 32, CF / 32, CE), 256>>>(w2, w2b, CF, CD);
        rmsnorm_split<<<CT, 256>>>(hid, ln1, xnbh, xnbl);
        qkv_b3<<<dim3(24, 16), 256, B3_SMEM>>>();
    }

    {
        int total = CT * (CH + CKV) * 32;
        rope_kernel<<<(total + 255) / 256, 256>>>(pos);
    }
    flash_bf16<<<dim3(CB * CH, CS / 128), 256, FL_SMEM>>>();
    oproj_b3<<<dim3(16, 16), 256, B3_SMEM>>>(hid);
    rmsnorm_dual<<<CT, 256>>>(h1, ln2, hn, hnb);
    cudaMemsetAsync(cnt, 0, CE * sizeof(int));
    router_kernel<<<(CT * 32 + 255) / 256, 256>>>(gw, out_scores);

    if (par) cudaStreamWaitEvent(0, s_ev2, 0);

    moe_up_bf16<<<dim3(CF / 64, CT / 128, CE), 256, MOEUP_SMEM>>>();
    moe_down_bf16<<<dim3(CD / 64, CT / 128, CE), 256, MOEDN_SMEM>>>();
    combine_kernel<<<(CT * CD / 4 + 255) / 256, 256>>>(out);
}

// round 16
// speedup vs baseline: 1.4672x; 1.0111x over previous
#include <cuda_runtime.h>
#include <cuda_bf16.h>
#include <math.h>
#include <stdint.h>

constexpr int CB = 2, CS = 1024, CD = 1024;
constexpr int CH = 16, CKV = 4, CHD = 64;
constexpr int CE = 8, CF = 2048;
constexpr int CT = CB * CS;
constexpr float CEPS = 1e-6f;

__device__ __nv_bfloat16 g_xnbh[CT * CD], g_xnbl[CT * CD];
__device__ float g_q  [CT * CH  * CHD];
__device__ float g_k  [CT * CKV * CHD];
__device__ __nv_bfloat16 g_kbh[CT * CKV * CHD], g_kbl[CT * CKV * CHD];
__device__ __nv_bfloat16 g_vbTh[CB * CKV * CHD * CS], g_vbTl[CB * CKV * CHD * CS];
__device__ __nv_bfloat16 g_atthb[CT * CH * CHD], g_attlb[CT * CH * CHD];
__device__ float g_h1 [CT * CD];
__device__ __nv_bfloat16 g_hnb[CT * CD];
__device__ int   g_cnt [CE];
__device__ int   g_tok [CE * CT];
__device__ float g_wsl [CE * CT];
__device__ int   g_slot[CT * 2];
__device__ __nv_bfloat16 g_hexpb[(size_t)CE * CT * CF];
__device__ float g_y   [(size_t)CE * CT * CD];
__device__ __nv_bfloat16 g_w1b[(size_t)CE * CF * CD];
__device__ __nv_bfloat16 g_w3b[(size_t)CE * CF * CD];
__device__ __nv_bfloat16 g_w2b[(size_t)CE * CD * CF];
__device__ __nv_bfloat16 g_wqTh[CD * CD],  g_wqTl[CD * CD];
__device__ __nv_bfloat16 g_wkTh[256 * CD], g_wkTl[256 * CD];
__device__ __nv_bfloat16 g_wvTh[256 * CD], g_wvTl[256 * CD];
__device__ __nv_bfloat16 g_woTh[CD * CD],  g_woTl[CD * CD];

#define U32(x) __float_as_uint(x)
#define MMAB(c, a, b0, b1) \
    asm volatile("mma.sync.aligned.m16n8k16.row.col.f32.bf16.bf16.f32 " \
        "{%0,%1,%2,%3}, {%4,%5,%6,%7}, {%8,%9}, {%0,%1,%2,%3};" \
        : "+f"((c)[0]), "+f"((c)[1]), "+f"((c)[2]), "+f"((c)[3]) \
        : "r"((a)[0]), "r"((a)[1]), "r"((a)[2]), "r"((a)[3]), "r"(b0), "r"(b1))

__device__ __forceinline__ void cpa16(uint32_t d, const void* s) {
    asm volatile("cp.async.ca.shared.global [%0], [%1], 16;" :: "r"(d), "l"(s));
}
#define CPC  asm volatile("cp.async.commit_group;")
#define CPW(n) asm volatile("cp.async.wait_group %0;" :: "n"(n))

__device__ __forceinline__ uint32_t packbf(float a, float b) {
    __nv_bfloat162 t = __floats2bfloat162_rn(a, b);
    return *(uint32_t*)&t;
}
__device__ __forceinline__ float bfl(__nv_bfloat16 h) { return __bfloat162float(h); }

// k-pair interleave permutation (within each 32-element block)
__device__ __forceinline__ int perm32(int d) {
    int pair = (d >> 1) & 15, e = d & 1;
    int p8 = pair & 7;
    int npos = (p8 < 4) ? (2 * p8) : (2 * (p8 - 4) + 1);
    int newpair = (pair & 8) | npos;
    return (d & ~31) | (newpair << 1) | e;
}

constexpr int MA_STG = 128 * 40;
constexpr int MB_STG = 64 * 40;
constexpr int PMA = 128 * 48;
constexpr int PMB = 64 * 48;

// ------------- bf16 permuted-layout core (MoE): LDS.64 fragments -------------
template<bool DUAL>
__device__ __forceinline__ void mma_core_bf16p(
    const __nv_bfloat16* pA0, const __nv_bfloat16* pA1,
    const __nv_bfloat16* pB1, const __nv_bfloat16* pB3,
    int K, __nv_bfloat16* sA, __nv_bfloat16* sB1, __nv_bfloat16* sB3, int tid,
    float c1[2][4][4], float c3[2][4][4])
{
    const int lane = tid & 31, wid = tid >> 5, grp = lane >> 2, tig = lane & 3;
    const int wm = (wid >> 1) * 32, wn = (wid & 1) * 32;
    uint32_t aA0 = (uint32_t)__cvta_generic_to_shared(sA) + (tid >> 2) * 96 + (tid & 3) * 16;
    uint32_t aA1 = aA0 + 64 * 96;
    uint32_t aB1 = (uint32_t)__cvta_generic_to_shared(sB1) + (tid >> 2) * 96 + (tid & 3) * 16;
    uint32_t aB3 = DUAL ? (uint32_t)__cvta_generic_to_shared(sB3) + (tid >> 2) * 96 + (tid & 3) * 16 : 0u;

    cpa16(aA0, pA0);
    cpa16(aA1, pA1);
    cpa16(aB1, pB1);
    if (DUAL) cpa16(aB3, pB3);
    CPC;

    int nt = K / 32;
    for (int t = 0; t < nt; ++t) {
        if (t + 1 < nt) {
            int k0 = (t + 1) * 32, st = (t + 1) & 1;
            cpa16(aA0 + st * (PMA * 2), pA0 + k0);
            cpa16(aA1 + st * (PMA * 2), pA1 + k0);
            cpa16(aB1 + st * (PMB * 2), pB1 + k0);
            if (DUAL) cpa16(aB3 + st * (PMB * 2), pB3 + k0);
            CPC; CPW(1);
        } else { CPW(0); }
        __syncthreads();
        const uint32_t* AU  = (const uint32_t*)(sA  + (t & 1) * PMA);
        const uint32_t* B1U = (const uint32_t*)(sB1 + (t & 1) * PMB);
        const uint32_t* B3U = (const uint32_t*)(sB3 + (t & 1) * PMB);
        #pragma unroll
        for (int ks = 0; ks < 2; ++ks) {
            int po = ks * 8 + 2 * tig;
            uint32_t a[2][4];
            #pragma unroll
            for (int i = 0; i < 2; ++i) {
                int r = wm + 16 * i + grp;
                uint2 t0 = *(const uint2*)&AU[r * 24 + po];
                uint2 t1 = *(const uint2*)&AU[(r + 8) * 24 + po];
                a[i][0] = t0.x; a[i][2] = t0.y;
                a[i][1] = t1.x; a[i][3] = t1.y;
            }
            #pragma unroll
            for (int j = 0; j < 4; ++j) {
                int n = wn + 8 * j + grp;
                uint2 b = *(const uint2*)&B1U[n * 24 + po];
                MMAB(c1[0][j], a[0], b.x, b.y);
                MMAB(c1[1][j], a[1], b.x, b.y);
                if (DUAL) {
                    uint2 d2 = *(const uint2*)&B3U[n * 24 + po];
                    MMAB(c3[0][j], a[0], d2.x, d2.y);
                    MMAB(c3[1][j], a[1], d2.x, d2.y);
                }
            }
        }
        __syncthreads();
    }
}

// ------------- bf16 3-term core (qkv/oproj) -------------
__device__ __forceinline__ void mma_core_bf16_3(
    const __nv_bfloat16* pAh0, const __nv_bfloat16* pAh1,
    const __nv_bfloat16* pAl0, const __nv_bfloat16* pAl1,
    const __nv_bfloat16* pBh, const __nv_bfloat16* pBl,
    int K, __nv_bfloat16* sm, int tid, float c[2][4][4])
{
    __nv_bfloat16* sAh = sm;
    __nv_bfloat16* sAl = sAh + 2 * MA_STG;
    __nv_bfloat16* sBh = sAl + 2 * MA_STG;
    __nv_bfloat16* sBl = sBh + 2 * MB_STG;
    const int lane = tid & 31, wid = tid >> 5, grp = lane >> 2, tig = lane & 3;
    const int wm = (wid >> 1) * 32, wn = (wid & 1) * 32;
    uint32_t off = (tid >> 2) * 80 + (tid & 3) * 16;
    uint32_t aAh0 = (uint32_t)__cvta_generic_to_shared(sAh) + off, aAh1 = aAh0 + 64 * 80;
    uint32_t aAl0 = (uint32_t)__cvta_generic_to_shared(sAl) + off, aAl1 = aAl0 + 64 * 80;
    uint32_t aBh  = (uint32_t)__cvta_generic_to_shared(sBh) + off;
    uint32_t aBl  = (uint32_t)__cvta_generic_to_shared(sBl) + off;

    cpa16(aAh0, pAh0); cpa16(aAh1, pAh1);
    cpa16(aAl0, pAl0); cpa16(aAl1, pAl1);
    cpa16(aBh, pBh);   cpa16(aBl, pBl);
    CPC;

    int nt = K / 32;
    for (int t = 0; t < nt; ++t) {
        if (t + 1 < nt) {
            int k0 = (t + 1) * 32, st = (t + 1) & 1;
            cpa16(aAh0 + st * (MA_STG * 2), pAh0 + k0);
            cpa16(aAh1 + st * (MA_STG * 2), pAh1 + k0);
            cpa16(aAl0 + st * (MA_STG * 2), pAl0 + k0);
            cpa16(aAl1 + st * (MA_STG * 2), pAl1 + k0);
            cpa16(aBh  + st * (MB_STG * 2), pBh + k0);
            cpa16(aBl  + st * (MB_STG * 2), pBl + k0);
            CPC; CPW(1);
        } else { CPW(0); }
        __syncthreads();
        const uint32_t* AhU = (const uint32_t*)(sAh + (t & 1) * MA_STG);
        const uint32_t* AlU = (const uint32_t*)(sAl + (t & 1) * MA_STG);
        const uint32_t* BhU = (const uint32_t*)(sBh + (t & 1) * MB_STG);
        const uint32_t* BlU = (const uint32_t*)(sBl + (t & 1) * MB_STG);
        #pragma unroll
        for (int ks = 0; ks < 2; ++ks) {
            int po = ks * 8;
            uint32_t ah[2][4], al[2][4];
            #pragma unroll
            for (int i = 0; i < 2; ++i) {
                int r = wm + 16 * i + grp;
                ah[i][0] = AhU[r * 20 + po + tig];
                ah[i][1] = AhU[(r + 8) * 20 + po + tig];
                ah[i][2] = AhU[r * 20 + po + tig + 4];
                ah[i][3] = AhU[(r + 8) * 20 + po + tig + 4];
                al[i][0] = AlU[r * 20 + po + tig];
                al[i][1] = AlU[(r + 8) * 20 + po + tig];
                al[i][2] = AlU[r * 20 + po + tig + 4];
                al[i][3] = AlU[(r + 8) * 20 + po + tig + 4];
            }
            #pragma unroll
            for (int j = 0; j < 4; ++j) {
                int n = wn + 8 * j + grp;
                uint32_t bh0 = BhU[n * 20 + po + tig], bh1 = BhU[n * 20 + po + tig + 4];
                uint32_t bl0 = BlU[n * 20 + po + tig], bl1 = BlU[n * 20 + po + tig + 4];
                #pragma unroll
                for (int i = 0; i < 2; ++i) {
                    MMAB(c[i][j], ah[i], bh0, bh1);
                    MMAB(c[i][j], ah[i], bl0, bl1);
                    MMAB(c[i][j], al[i], bh0, bh1);
                }
            }
        }
        __syncthreads();
    }
}

// ---------------- MoE weight transpose (k-permuted), full grid ----------------
__global__ void transpose_w(const float* __restrict__ src, __nv_bfloat16* __restrict__ dst,
                            int R, int C) {
    __shared__ float t[32][33];
    const float* s = src + (size_t)blockIdx.z * R * C;
    __nv_bfloat16* d = dst + (size_t)blockIdx.z * R * C;
    int r0 = blockIdx.y * 32, c0 = blockIdx.x * 32;
    int tx = threadIdx.x & 31, ty = threadIdx.x >> 5;
    #pragma unroll
    for (int i = 0; i < 4; ++i) {
        int r = ty + i * 8;
        t[r][tx] = s[(size_t)(r0 + r) * C + c0 + tx];
    }
    __syncthreads();
    int ptx = perm32(tx);
    #pragma unroll
    for (int i = 0; i < 4; ++i) {
        int r = ty + i * 8;
        d[(size_t)(c0 + r) * R + r0 + ptx] = __float2bfloat16_rn(t[tx][r]);
    }
}

// qkv/o weights: unpermuted hi/lo split
__global__ void transpose_w_split(const float* __restrict__ src,
                                  __nv_bfloat16* __restrict__ dh, __nv_bfloat16* __restrict__ dl,
                                  int R, int C) {
    __shared__ float t[32][33];
    int r0 = blockIdx.y * 32, c0 = blockIdx.x * 32;
    int tx = threadIdx.x & 31, ty = threadIdx.x >> 5;
    #pragma unroll
    for (int i = 0; i < 4; ++i) {
        int r = ty + i * 8;
        t[r][tx] = src[(size_t)(r0 + r) * C + c0 + tx];
    }
    __syncthreads();
    #pragma unroll
    for (int i = 0; i < 4; ++i) {
        int r = ty + i * 8;
        float v = t[tx][r];
        __nv_bfloat16 h = __float2bfloat16_rn(v);
        size_t idx = (size_t)(c0 + r) * R + r0 + tx;
        dh[idx] = h;
        dl[idx] = __float2bfloat16_rn(v - __bfloat162float(h));
    }
}

// ---------------- RMSNorm producing bf16 hi/lo ----------------
__global__ void rmsnorm_split(const float* __restrict__ x, const float* __restrict__ w,
                              __nv_bfloat16* __restrict__ oh, __nv_bfloat16* __restrict__ ol) {
    int t = blockIdx.x;
    const float* xr = x + (size_t)t * CD;
    float ss = 0.f;
    for (int d = threadIdx.x; d < CD; d += 256) { float v = xr[d]; ss += v * v; }
    __shared__ float red[256];
    red[threadIdx.x] = ss;
    __syncthreads();
    for (int s = 128; s > 0; s >>= 1) {
        if (threadIdx.x < s) red[threadIdx.x] += red[threadIdx.x + s];
        __syncthreads();
    }
    __shared__ float rinv;
    if (threadIdx.x == 0) rinv = rsqrtf(red[0] * (1.f / CD) + CEPS);
    __syncthreads();
    for (int d = threadIdx.x; d < CD; d += 256) {
        float v = xr[d] * rinv * w[d];
        size_t idx = (size_t)t * CD + d;
        __nv_bfloat16 h = __float2bfloat16_rn(v);
        oh[idx] = h;
        ol[idx] = __float2bfloat16_rn(v - __bfloat162float(h));
    }
}

// ---------------- FUSED rmsnorm2 + router: bf16 hnb + scores + top-2 dispatch ----------------
__global__ void rmsnorm_router(const float* __restrict__ x, const float* __restrict__ w,
                               const float* __restrict__ Gw, float* __restrict__ scores_out,
                               __nv_bfloat16* __restrict__ outb) {
    int t = blockIdx.x, tid = threadIdx.x;
    const float* xr = x + (size_t)t * CD;
    float xv[4];
    float ss = 0.f;
    #pragma unroll
    for (int i = 0; i < 4; ++i) {
        xv[i] = xr[tid + i * 256];
        ss += xv[i] * xv[i];
    }
    __shared__ float red[256];
    red[tid] = ss;
    __syncthreads();
    for (int s = 128; s > 0; s >>= 1) {
        if (tid < s) red[tid] += red[tid + s];
        __syncthreads();
    }
    __shared__ float rinv;
    if (tid == 0) rinv = rsqrtf(red[0] * (1.f / CD) + CEPS);
    __syncthreads();

    float acc[CE] = {};
    #pragma unroll
    for (int i = 0; i < 4; ++i) {
        int d = tid + i * 256;
        float v = xv[i] * rinv * w[d];
        outb[(size_t)t * CD + perm32(d)] = __float2bfloat16_rn(v);
        const float* gr = Gw + (size_t)d * CE;
        #pragma unroll
        for (int e = 0; e < CE; ++e) acc[e] += v * gr[e];
    }
    int lane = tid & 31, wid = tid >> 5;
    #pragma unroll
    for (int off = 16; off; off >>= 1)
        #pragma unroll
        for (int e = 0; e < CE; ++e) acc[e] += __shfl_down_sync(0xffffffffu, acc[e], off);
    __shared__ float wacc[8][CE];
    if (lane == 0) {
        #pragma unroll
        for (int e = 0; e < CE; ++e) wacc[wid][e] = acc[e];
    }
    __syncthreads();
    if (tid == 0) {
        float p[CE];
        #pragma unroll
        for (int e = 0; e < CE; ++e) {
            float s = 0.f;
            #pragma unroll
            for (int w8 = 0; w8 < 8; ++w8) s += wacc[w8][e];
            p[e] = s;
        }
        float mx = p[0];
        #pragma unroll
        for (int e = 1; e < CE; ++e) mx = fmaxf(mx, p[e]);
        float sum = 0.f;
        #pragma unroll
        for (int e = 0; e < CE; ++e) { p[e] = expf(p[e] - mx); sum += p[e]; }
        float inv = 1.f / sum;
        #pragma unroll
        for (int e = 0; e < CE; ++e) { p[e] *= inv; scores_out[(size_t)t * CE + e] = p[e]; }
        int e0 = 0; float b0 = p[0];
        #pragma unroll
        for (int e = 1; e < CE; ++e) if (p[e] > b0) { b0 = p[e]; e0 = e; }
        int e1 = -1; float b1 = -1.f;
        #pragma unroll
        for (int e = 0; e < CE; ++e) if (e != e0 && p[e] > b1) { b1 = p[e]; e1 = e; }
        float wsum = b0 + b1;
        int p0 = atomicAdd(&g_cnt[e0], 1);
        g_tok[e0 * CT + p0] = t; g_wsl[e0 * CT + p0] = b0 / wsum;
        g_slot[t * 2 + 0] = e0 * CT + p0;
        int p1 = atomicAdd(&g_cnt[e1], 1);
        g_tok[e1 * CT + p1] = t; g_wsl[e1 * CT + p1] = b1 / wsum;
        g_slot[t * 2 + 1] = e1 * CT + p1;
    }
}

// ---------------- fused QKV projection (3-term bf16); V written transposed bf16 hi/lo ----
constexpr size_t B3_SMEM = (size_t)(4 * MA_STG + 4 * MB_STG) * 2;
__global__ __launch_bounds__(256) void qkv_b3() {
    extern __shared__ __nv_bfloat16 bsm[];
    int n0 = blockIdx.x * 64, m0 = blockIdx.y * 128, tid = threadIdx.x;
    const __nv_bfloat16 *Bh, *Bl; float* C; int ldc, nc; bool isV = false;
    if (n0 < 1024)      { Bh = g_wqTh; Bl = g_wqTl; C = g_q; ldc = 1024; nc = n0; }
    else if (n0 < 1280) { Bh = g_wkTh; Bl = g_wkTl; C = g_k; ldc = 256;  nc = n0 - 1024; }
    else                { Bh = g_wvTh; Bl = g_wvTl; C = nullptr; ldc = 256; nc = n0 - 1280; isV = true; }
    const __nv_bfloat16* pAh0 = g_xnbh + (size_t)(m0 + (tid >> 2)) * CD + (tid & 3) * 8;
    const __nv_bfloat16* pAh1 = pAh0 + (size_t)64 * CD;
    const __nv_bfloat16* pAl0 = g_xnbl + (size_t)(m0 + (tid >> 2)) * CD + (tid & 3) * 8;
    const __nv_bfloat16* pAl1 = pAl0 + (size_t)64 * CD;
    const __nv_bfloat16* pBh  = Bh + (size_t)(nc + (tid >> 2)) * CD + (tid & 3) * 8;
    const __nv_bfloat16* pBl  = Bl + (size_t)(nc + (tid >> 2)) * CD + (tid & 3) * 8;
    float c[2][4][4] = {};
    mma_core_bf16_3(pAh0, pAh1, pAl0, pAl1, pBh, pBl, CD, bsm, tid, c);
    int lane = tid & 31, wid = tid >> 5, grp = lane >> 2, tig = lane & 3;
    int wm = (wid >> 1) * 32, wn = (wid & 1) * 32;
    if (!isV) {
        #pragma unroll
        for (int i = 0; i < 2; ++i) {
            int r = m0 + wm + 16 * i + grp;
            #pragma unroll
            for (int j = 0; j < 4; ++j) {
                int cc = nc + wn + 8 * j + 2 * tig;
                *(float2*)&C[(size_t)r * ldc + cc]       = make_float2(c[i][j][0], c[i][j][1]);
                *(float2*)&C[(size_t)(r + 8) * ldc + cc] = make_float2(c[i][j][2], c[i][j][3]);
            }
        }
    } else {
        #pragma unroll
        for (int i = 0; i < 2; ++i) {
            #pragma unroll
            for (int j = 0; j < 4; ++j) {
                int cc = nc + wn + 8 * j + 2 * tig;
                #pragma unroll
                for (int u = 0; u < 4; ++u) {
                    int r = m0 + wm + 16 * i + grp + (u >> 1) * 8;
                    int ccc = cc + (u & 1);
                    float v = c[i][j][u];
                    int bb = r >> 10, ss = r & 1023;
                    size_t o = ((size_t)(bb * CKV + (ccc >> 6)) * CHD + (ccc & 63)) * CS + ss;
                    __nv_bfloat16 hv = __float2bfloat16_rn(v);
                    g_vbTh[o] = hv;
                    g_vbTl[o] = __float2bfloat16_rn(v - bfl(hv));
                }
            }
        }
    }
}

// ---------------- O projection + residual (3-term bf16) ----------------
__global__ __launch_bounds__(256) void oproj_b3(const float* __restrict__ Res) {
    extern __shared__ __nv_bfloat16 bsm[];
    int n0 = blockIdx.x * 64, m0 = blockIdx.y * 128, tid = threadIdx.x;
    const __nv_bfloat16* pAh0 = g_atthb + (size_t)(m0 + (tid >> 2)) * CD + (tid & 3) * 8;
    const __nv_bfloat16* pAh1 = pAh0 + (size_t)64 * CD;
    const __nv_bfloat16* pAl0 = g_attlb + (size_t)(m0 + (tid >> 2)) * CD + (tid & 3) * 8;
    const __nv_bfloat16* pAl1 = pAl0 + (size_t)64 * CD;
    const __nv_bfloat16* pBh  = g_woTh + (size_t)(n0 + (tid >> 2)) * CD + (tid & 3) * 8;
    const __nv_bfloat16* pBl  = g_woTl + (size_t)(n0 + (tid >> 2)) * CD + (tid & 3) * 8;
    float c[2][4][4] = {};
    mma_core_bf16_3(pAh0, pAh1, pAl0, pAl1, pBh, pBl, CD, bsm, tid, c);
    int lane = tid & 31, wid = tid >> 5, grp = lane >> 2, tig = lane & 3;
    int wm = (wid >> 1) * 32, wn = (wid & 1) * 32;
    #pragma unroll
    for (int i = 0; i < 2; ++i) {
        int r = m0 + wm + 16 * i + grp;
        #pragma unroll
        for (int j = 0; j < 4; ++j) {
            int cc = n0 + wn + 8 * j + 2 * tig;
            size_t i0 = (size_t)r * CD + cc, i1 = (size_t)(r + 8) * CD + cc;
            float2 r0 = *(const float2*)&Res[i0], r1 = *(const float2*)&Res[i1];
            *(float2*)&g_h1[i0] = make_float2(c[i][j][0] + r0.x, c[i][j][1] + r0.y);
            *(float2*)&g_h1[i1] = make_float2(c[i][j][2] + r1.x, c[i][j][3] + r1.y);
        }
    }
}

// ---------------- RoPE: q in-place fp32; k -> bf16 hi/lo ----------------
__global__ void rope_kernel(const int* __restrict__ pos_ids) {
    int idx = blockIdx.x * 256 + threadIdx.x;
    const int nq = CT * CH * 32, nk = CT * CKV * 32;
    if (idx >= nq + nk) return;
    if (idx < nq) {
        int i = idx & 31; int th = idx >> 5; int h = th % CH; int t = th / CH;
        float* base = g_q + ((size_t)t * CH + h) * CHD;
        float p = (float)pos_ids[t];
        float freq = expf(-(2.f * i / (float)CHD) * logf(10000.f));
        float ang = p * freq, cv = cosf(ang), sv = sinf(ang);
        float x0 = base[i], x1 = base[i + 32];
        base[i] = x0 * cv - x1 * sv;
        base[i + 32] = x1 * cv + x0 * sv;
    } else {
        int id2 = idx - nq;
        int i = id2 & 31; int th = id2 >> 5; int h = th % CKV; int t = th / CKV;
        size_t boff = ((size_t)t * CKV + h) * CHD;
        const float* base = g_k + boff;
        float p = (float)pos_ids[t];
        float freq = expf(-(2.f * i / (float)CHD) * logf(10000.f));
        float ang = p * freq, cv = cosf(ang), sv = sinf(ang);
        float x0 = base[i], x1 = base[i + 32];
        float y0 = x0 * cv - x1 * sv;
        float y1 = x1 * cv + x0 * sv;
        __nv_bfloat16 h0 = __float2bfloat16_rn(y0), h1 = __float2bfloat16_rn(y1);
        g_kbh[boff + i]      = h0;
        g_kbl[boff + i]      = __float2bfloat16_rn(y0 - bfl(h0));
        g_kbh[boff + i + 32] = h1;
        g_kbl[boff + i + 32] = __float2bfloat16_rn(y1 - bfl(h1));
    }
}

// ---------------- flash attention (cp.async double-buffered K/V) ----------------
constexpr int FL_STG = 64 * 72;
constexpr int FL_SMEM = 128 * 72 * 4 + 8 * FL_STG * 2;
__global__ __launch_bounds__(256) void flash_bf16() {
    extern __shared__ char fsm[];
    float* Qs = (float*)fsm;
    uint32_t* PhU = (uint32_t*)fsm;
    uint32_t* PlU = PhU + 128 * 36;
    __nv_bfloat16* Kh = (__nv_bfloat16*)(fsm + 128 * 72 * 4);
    __nv_bfloat16* Kl = Kh + 2 * FL_STG;
    __nv_bfloat16* Vh = Kl + 2 * FL_STG;
    __nv_bfloat16* Vl = Vh + 2 * FL_STG;

    int bh = blockIdx.x, qt = 7 - blockIdx.y;
    int b = bh >> 4, h = bh & 15, kvh = h >> 2;
    int tid = threadIdx.x, lane = tid & 31, warp = tid >> 5, grp = lane >> 2, tig = lane & 3;
    int rl0 = warp * 16 + grp;

    uint32_t aKh = (uint32_t)__cvta_generic_to_shared(Kh);
    uint32_t aKl = (uint32_t)__cvta_generic_to_shared(Kl);
    uint32_t aVh = (uint32_t)__cvta_generic_to_shared(Vh);
    uint32_t aVl = (uint32_t)__cvta_generic_to_shared(Vl);

    auto load_tile = [&](int kt, int st) {
        uint32_t so = st * (FL_STG * 2);
        #pragma unroll
        for (int it = 0; it < 2; ++it) {
            int idx = tid + it * 256;
            int n = idx >> 3, c8 = (idx & 7) * 8;
            uint32_t dsto = so + (uint32_t)(n * 144 + c8 * 2);
            size_t gk = ((size_t)(b * CS + kt * 64 + n) * CKV + kvh) * CHD + c8;
            size_t gv = ((size_t)(b * CKV + kvh) * CHD + n) * CS + kt * 64 + c8;
            cpa16(aKh + dsto, g_kbh + gk);
            cpa16(aKl + dsto, g_kbl + gk);
            cpa16(aVh + dsto, g_vbTh + gv);
            cpa16(aVl + dsto, g_vbTl + gv);
        }
    };

    #pragma unroll
    for (int it = 0; it < 8; ++it) {
        int idx = tid + it * 256;
        int r = idx >> 4, d4 = (idx & 15) * 4;
        float4 qv = *(const float4*)&g_q[((size_t)(b * CS + qt * 128 + r) * CH + h) * CHD + d4];
        Qs[r * 72 + d4]     = qv.x * 0.125f;
        Qs[r * 72 + d4 + 1] = qv.y * 0.125f;
        Qs[r * 72 + d4 + 2] = qv.z * 0.125f;
        Qs[r * 72 + d4 + 3] = qv.w * 0.125f;
    }
    load_tile(0, 0);
    CPC;
    __syncthreads();

    uint32_t qh[4][4], ql[4][4];
    #pragma unroll
    for (int ks = 0; ks < 4; ++ks)
        #pragma unroll
        for (int u = 0; u < 4; ++u) {
            int kk = ks * 16 + 2 * (tig + (u >> 1) * 4);
            int rr = rl0 + (u & 1) * 8;
            float x0 = Qs[rr * 72 + kk], x1 = Qs[rr * 72 + kk + 1];
            __nv_bfloat16 h0 = __float2bfloat16_rn(x0), h1 = __float2bfloat16_rn(x1);
            qh[ks][u] = packbf(bfl(h0), bfl(h1));
            ql[ks][u] = packbf(x0 - bfl(h0), x1 - bfl(h1));
        }

    float o[8][4] = {};
    float m0v = -INFINITY, m1v = -INFINITY, l0v = 0.f, l1v = 0.f;
    int ntiles = 2 * (qt + 1);

    for (int kt = 0; kt < ntiles; ++kt) {
        if (kt + 1 < ntiles) {
            load_tile(kt + 1, (kt + 1) & 1);
            CPC; CPW(1);
        } else { CPW(0); }
        __syncthreads();
        const uint32_t* KhU = (const uint32_t*)(Kh + (kt & 1) * FL_STG);
        const uint32_t* KlU = (const uint32_t*)(Kl + (kt & 1) * FL_STG);
        const uint32_t* VhU = (const uint32_t*)(Vh + (kt & 1) * FL_STG);
        const uint32_t* VlU = (const uint32_t*)(Vl + (kt & 1) * FL_STG);

        float s[8][4] = {};
        #pragma unroll
        for (int ks = 0; ks < 4; ++ks) {
            int po = ks * 8;
            #pragma unroll
            for (int j = 0; j < 8; ++j) {
                int n = 8 * j + grp;
                uint32_t bh0 = KhU[n * 36 + po + tig], bh1 = KhU[n * 36 + po + tig + 4];
                uint32_t bl0 = KlU[n * 36 + po + tig], bl1 = KlU[n * 36 + po + tig + 4];
                MMAB(s[j], qh[ks], bh0, bh1);
                MMAB(s[j], qh[ks], bl0, bl1);
                MMAB(s[j], ql[ks], bh0, bh1);
            }
        }
        if (kt >= 2 * qt) {
            int rg0 = qt * 128 + rl0;
            #pragma unroll
            for (int j = 0; j < 8; ++j) {
                int cg = kt * 64 + 8 * j + 2 * tig;
                if (cg     > rg0)     s[j][0] = -INFINITY;
                if (cg + 1 > rg0)     s[j][1] = -INFINITY;
                if (cg     > rg0 + 8) s[j][2] = -INFINITY;
                if (cg + 1 > rg0 + 8) s[j][3] = -INFINITY;
            }
        }
        float mx0 = -INFINITY, mx1 = -INFINITY;
        #pragma unroll
        for (int j = 0; j < 8; ++j) {
            mx0 = fmaxf(mx0, fmaxf(s[j][0], s[j][1]));
            mx1 = fmaxf(mx1, fmaxf(s[j][2], s[j][3]));
        }
        mx0 = fmaxf(mx0, __shfl_xor_sync(0xffffffffu, mx0, 1));
        mx0 = fmaxf(mx0, __shfl_xor_sync(0xffffffffu, mx0, 2));
        mx1 = fmaxf(mx1, __shfl_xor_sync(0xffffffffu, mx1, 1));
        mx1 = fmaxf(mx1, __shfl_xor_sync(0xffffffffu, mx1, 2));
        float mn0 = fmaxf(m0v, mx0), mn1 = fmaxf(m1v, mx1);
        float al0 = expf(m0v - mn0), al1 = expf(m1v - mn1);
        float s0 = 0.f, s1 = 0.f;
        #pragma unroll
        for (int j = 0; j < 8; ++j) {
            s[j][0] = expf(s[j][0] - mn0); s[j][1] = expf(s[j][1] - mn0);
            s[j][2] = expf(s[j][2] - mn1); s[j][3] = expf(s[j][3] - mn1);
            s0 += s[j][0] + s[j][1];
            s1 += s[j][2] + s[j][3];
        }
        s0 += __shfl_xor_sync(0xffffffffu, s0, 1); s0 += __shfl_xor_sync(0xffffffffu, s0, 2);
        s1 += __shfl_xor_sync(0xffffffffu, s1, 1); s1 += __shfl_xor_sync(0xffffffffu, s1, 2);
        l0v = l0v * al0 + s0; l1v = l1v * al1 + s1;
        m0v = mn0; m1v = mn1;
        #pragma unroll
        for (int j = 0; j < 8; ++j) {
            o[j][0] *= al0; o[j][1] *= al0; o[j][2] *= al1; o[j][3] *= al1;
        }
        #pragma unroll
        for (int j = 0; j < 8; ++j) {
            int ci = 4 * j + tig;
            __nv_bfloat16 p0 = __float2bfloat16_rn(s[j][0]), p1 = __float2bfloat16_rn(s[j][1]);
            __nv_bfloat16 p2 = __float2bfloat16_rn(s[j][2]), p3 = __float2bfloat16_rn(s[j][3]);
            PhU[rl0 * 36 + ci]       = packbf(bfl(p0), bfl(p1));
            PhU[(rl0 + 8) * 36 + ci] = packbf(bfl(p2), bfl(p3));
            PlU[rl0 * 36 + ci]       = packbf(s[j][0] - bfl(p0), s[j][1] - bfl(p1));
            PlU[(rl0 + 8) * 36 + ci] = packbf(s[j][2] - bfl(p2), s[j][3] - bfl(p3));
        }
        __syncwarp();
        #pragma unroll
        for (int ks = 0; ks < 4; ++ks) {
            int po = ks * 8;
            uint32_t pa[4], pla[4];
            pa[0]  = PhU[rl0 * 36 + po + tig];
            pa[1]  = PhU[(rl0 + 8) * 36 + po + tig];
            pa[2]  = PhU[rl0 * 36 + po + tig + 4];
            pa[3]  = PhU[(rl0 + 8) * 36 + po + tig + 4];
            pla[0] = PlU[rl0 * 36 + po + tig];
            pla[1] = PlU[(rl0 + 8) * 36 + po + tig];
            pla[2] = PlU[rl0 * 36 + po + tig + 4];
            pla[3] = PlU[(rl0 + 8) * 36 + po + tig + 4];
            #pragma unroll
            for (int j = 0; j < 8; ++j) {
                int n = 8 * j + grp;
                uint32_t vh0 = VhU[n * 36 + po + tig], vh1 = VhU[n * 36 + po + tig + 4];
                uint32_t vl0 = VlU[n * 36 + po + tig], vl1 = VlU[n * 36 + po + tig + 4];
                MMAB(o[j], pa, vh0, vh1);
                MMAB(o[j], pa, vl0, vl1);
                MMAB(o[j], pla, vh0, vh1);
            }
        }
        __syncthreads();
    }

    float i0 = 1.f / l0v, i1 = 1.f / l1v;
    size_t t0 = (size_t)(b * CS + qt * 128 + rl0);
    #pragma unroll
    for (int j = 0; j < 8; ++j) {
        int d = 8 * j + 2 * tig;
        size_t i0a = (t0 * CH + h) * CHD + d;
        size_t i1a = ((t0 + 8) * CH + h) * CHD + d;
        float v00 = o[j][0] * i0, v01 = o[j][1] * i0;
        float v10 = o[j][2] * i1, v11 = o[j][3] * i1;
        __nv_bfloat16 h00 = __float2bfloat16_rn(v00), h01 = __float2bfloat16_rn(v01);
        __nv_bfloat16 h10 = __float2bfloat16_rn(v10), h11 = __float2bfloat16_rn(v11);
        *(__nv_bfloat162*)&g_atthb[i0a] = __nv_bfloat162(h00, h01);
        *(__nv_bfloat162*)&g_attlb[i0a] = __nv_bfloat162(
            __float2bfloat16_rn(v00 - bfl(h00)), __float2bfloat16_rn(v01 - bfl(h01)));
        *(__nv_bfloat162*)&g_atthb[i1a] = __nv_bfloat162(h10, h11);
        *(__nv_bfloat162*)&g_attlb[i1a] = __nv_bfloat162(
            __float2bfloat16_rn(v10 - bfl(h10)), __float2bfloat16_rn(v11 - bfl(h11)));
    }
}

// ---------------- MoE up (bf16, permuted layout, dynamic smem) ----------------
constexpr size_t MOEUP_SMEM = (size_t)(2 * PMA + 4 * PMB) * 2;
__global__ __launch_bounds__(256, 2) void moe_up_bf16() {
    int e = blockIdx.z, cnt = g_cnt[e], r0 = blockIdx.y * 128;
    if (r0 >= cnt) return;
    int f0 = blockIdx.x * 64, tid = threadIdx.x;
    extern __shared__ __nv_bfloat16 msm[];
    __nv_bfloat16* sA  = msm;
    __nv_bfloat16* sB1 = sA + 2 * PMA;
    __nv_bfloat16* sB3 = sB1 + 2 * PMB;
    __shared__ int toks[128]; __shared__ float wrow[128];
    if (tid < 128) {
        int rr = r0 + tid; bool ok = rr < cnt;
        toks[tid] = ok ? g_tok[e * CT + rr] : g_tok[e * CT];
        wrow[tid] = ok ? g_wsl[e * CT + rr] : 0.f;
    }
    __syncthreads();
    const __nv_bfloat16* pA0 = g_hnb + (size_t)toks[tid >> 2] * CD + (tid & 3) * 8;
    const __nv_bfloat16* pA1 = g_hnb + (size_t)toks[(tid >> 2) + 64] * CD + (tid & 3) * 8;
    const __nv_bfloat16* pB1 = g_w1b + (size_t)e * CF * CD + (size_t)(f0 + (tid >> 2)) * CD + (tid & 3) * 8;
    const __nv_bfloat16* pB3 = g_w3b + (size_t)e * CF * CD + (size_t)(f0 + (tid >> 2)) * CD + (tid & 3) * 8;
    float c1[2][4][4] = {}, c3[2][4][4] = {};
    mma_core_bf16p<true>(pA0, pA1, pB1, pB3, CD, sA, sB1, sB3, tid, c1, c3);
    int lane = tid & 31, wid = tid >> 5, grp = lane >> 2, tig = lane & 3;
    int wm = (wid >> 1) * 32, wn = (wid & 1) * 32;
    #pragma unroll
    for (int i = 0; i < 2; ++i) {
        int rloc = wm + 16 * i + grp;
        float w0 = wrow[rloc], w1v = wrow[rloc + 8];
        size_t rr0 = (size_t)e * CT + r0 + rloc;
        #pragma unroll
        for (int j = 0; j < 4; ++j) {
            int cc = f0 + wn + 8 * j + 2 * tig;
            int P = cc >> 1, p8 = P & 7;
            int npos = (p8 < 4) ? (2 * p8) : (2 * (p8 - 4) + 1);
            int ncc = (((P & ~7) | npos) << 1);
            float x0 = c1[i][j][0], x1 = c1[i][j][1], x2 = c1[i][j][2], x3 = c1[i][j][3];
            float y0 = (x0 / (1.f + expf(-x0))) * c3[i][j][0] * w0;
            float y1 = (x1 / (1.f + expf(-x1))) * c3[i][j][1] * w0;
            float y2 = (x2 / (1.f + expf(-x2))) * c3[i][j][2] * w1v;
            float y3 = (x3 / (1.f + expf(-x3))) * c3[i][j][3] * w1v;
            *(__nv_bfloat162*)&g_hexpb[rr0 * CF + ncc]       = __floats2bfloat162_rn(y0, y1);
            *(__nv_bfloat162*)&g_hexpb[(rr0 + 8) * CF + ncc] = __floats2bfloat162_rn(y2, y3);
        }
    }
}

// ---------------- MoE down (bf16, permuted layout, dynamic smem) ----------------
constexpr size_t MOEDN_SMEM = (size_t)(2 * PMA + 2 * PMB) * 2;
__global__ __launch_bounds__(256, 2) void moe_down_bf16() {
    int e = blockIdx.z, cnt = g_cnt[e], r0 = blockIdx.y * 128;
    if (r0 >= cnt) return;
    int n0 = blockIdx.x * 64, tid = threadIdx.x;
    extern __shared__ __nv_bfloat16 msm[];
    __nv_bfloat16* sA = msm;
    __nv_bfloat16* sB = sA + 2 * PMA;
    const __nv_bfloat16* pA0 = g_hexpb + (size_t)(e * CT + r0 + (tid >> 2)) * CF + (tid & 3) * 8;
    const __nv_bfloat16* pA1 = pA0 + (size_t)64 * CF;
    const __nv_bfloat16* pB  = g_w2b + (size_t)e * CD * CF + (size_t)(n0 + (tid >> 2)) * CF + (tid & 3) * 8;
    float c1[2][4][4] = {};
    mma_core_bf16p<false>(pA0, pA1, pB, pB, CF, sA, sB, sB, tid, c1, c1);
    float* C = g_y + ((size_t)e * CT + r0) * CD;
    int lane = tid & 31, wid = tid >> 5, grp = lane >> 2, tig = lane & 3;
    int wm = (wid >> 1) * 32, wn = (wid & 1) * 32;
    #pragma unroll
    for (int i = 0; i < 2; ++i) {
        int rloc = wm + 16 * i + grp;
        #pragma unroll
        for (int j = 0; j < 4; ++j) {
            int cc = n0 + wn + 8 * j + 2 * tig;
            *(float2*)&C[(size_t)rloc * CD + cc]       = make_float2(c1[i][j][0], c1[i][j][1]);
            *(float2*)&C[(size_t)(rloc + 8) * CD + cc] = make_float2(c1[i][j][2], c1[i][j][3]);
        }
    }
}

// ---------------- combine (float4 vectorized) ----------------
__global__ void combine_kernel(float* __restrict__ out) {
    int idx = blockIdx.x * 256 + threadIdx.x;
    if (idx >= CT * CD / 4) return;
    int e4 = idx * 4;
    int t = e4 >> 10, d = e4 & 1023;
    int s0 = g_slot[t * 2 + 0], s1 = g_slot[t * 2 + 1];
    float4 a = *(const float4*)&g_h1[e4];
    float4 y0 = *(const float4*)&g_y[(size_t)s0 * CD + d];
    float4 y1 = *(const float4*)&g_y[(size_t)s1 * CD + d];
    float4 r;
    r.x = a.x + y0.x + y1.x;
    r.y = a.y + y0.y + y1.y;
    r.z = a.z + y0.z + y1.z;
    r.w = a.w + y0.w + y1.w;
    *(float4*)&out[e4] = r;
}

// ---------------- stream/event infrastructure ----------------
static cudaStream_t s_s1 = nullptr, s_s2 = nullptr;
static cudaEvent_t  s_evRoot = nullptr, s_ev1 = nullptr, s_ev2 = nullptr;
static struct StreamInit {
    StreamInit() {
        cudaFree(0);
        if (cudaStreamCreateWithFlags(&s_s1, cudaStreamNonBlocking) != cudaSuccess) s_s1 = nullptr;
        if (cudaStreamCreateWithFlags(&s_s2, cudaStreamNonBlocking) != cudaSuccess) s_s2 = nullptr;
        if (cudaEventCreateWithFlags(&s_evRoot, cudaEventDisableTiming) != cudaSuccess) s_evRoot = nullptr;
        if (cudaEventCreateWithFlags(&s_ev1, cudaEventDisableTiming) != cudaSuccess) s_ev1 = nullptr;
        if (cudaEventCreateWithFlags(&s_ev2, cudaEventDisableTiming) != cudaSuccess) s_ev2 = nullptr;
    }
} s_streamInit;

// ---------------- launcher ----------------
extern "C" void kernel_launch(void* const* d_in, const int* in_sizes, int n_in,
                              void* d_out, int out_size) {
    const float* hid = (const float*)d_in[0];
    const int*   pos = (const int*)  d_in[1];
    const float* ln1 = (const float*)d_in[3];
    const float* ln2 = (const float*)d_in[4];
    const float* wq  = (const float*)d_in[5];
    const float* wk  = (const float*)d_in[6];
    const float* wv  = (const float*)d_in[7];
    const float* wo  = (const float*)d_in[8];
    const float* gw  = (const float*)d_in[9];
    const float* w1  = (const float*)d_in[10];
    const float* w3  = (const float*)d_in[11];
    const float* w2  = (const float*)d_in[12];
    float* out        = (float*)d_out;
    float* out_scores = out + (size_t)CT * CD;

    __nv_bfloat16 *xnbh, *xnbl, *hnb, *w1b, *w3b, *w2b;
    __nv_bfloat16 *wqTh, *wqTl, *wkTh, *wkTl, *wvTh, *wvTl, *woTh, *woTl;
    cudaGetSymbolAddress((void**)&xnbh, g_xnbh);
    cudaGetSymbolAddress((void**)&xnbl, g_xnbl);
    cudaGetSymbolAddress((void**)&hnb, g_hnb);
    cudaGetSymbolAddress((void**)&w1b, g_w1b);
    cudaGetSymbolAddress((void**)&w3b, g_w3b);
    cudaGetSymbolAddress((void**)&w2b, g_w2b);
    cudaGetSymbolAddress((void**)&wqTh, g_wqTh); cudaGetSymbolAddress((void**)&wqTl, g_wqTl);
    cudaGetSymbolAddress((void**)&wkTh, g_wkTh); cudaGetSymbolAddress((void**)&wkTl, g_wkTl);
    cudaGetSymbolAddress((void**)&wvTh, g_wvTh); cudaGetSymbolAddress((void**)&wvTl, g_wvTl);
    cudaGetSymbolAddress((void**)&woTh, g_woTh); cudaGetSymbolAddress((void**)&woTl, g_woTl);
    float* h1; cudaGetSymbolAddress((void**)&h1, g_h1);
    int*  cnt; cudaGetSymbolAddress((void**)&cnt, g_cnt);

    cudaFuncSetAttribute(flash_bf16, cudaFuncAttributeMaxDynamicSharedMemorySize, FL_SMEM);
    cudaFuncSetAttribute(qkv_b3,   cudaFuncAttributeMaxDynamicSharedMemorySize, B3_SMEM);
    cudaFuncSetAttribute(oproj_b3, cudaFuncAttributeMaxDynamicSharedMemorySize, B3_SMEM);
    cudaFuncSetAttribute(moe_up_bf16,   cudaFuncAttributeMaxDynamicSharedMemorySize, MOEUP_SMEM);
    cudaFuncSetAttribute(moe_down_bf16, cudaFuncAttributeMaxDynamicSharedMemorySize, MOEDN_SMEM);

    bool par = s_s1 && s_s2 && s_evRoot && s_ev1 && s_ev2;

    if (par) {
        cudaEventRecord(s_evRoot, 0);
        cudaStreamWaitEvent(s_s1, s_evRoot, 0);
        cudaStreamWaitEvent(s_s2, s_evRoot, 0);

        transpose_w_split<<<dim3(32, 32), 256, 0, s_s1>>>(wq, wqTh, wqTl, CD, CD);
        transpose_w_split<<<dim3(8, 32),  256, 0, s_s1>>>(wk, wkTh, wkTl, CD, 256);
        transpose_w_split<<<dim3(8, 32),  256, 0, s_s1>>>(wv, wvTh, wvTl, CD, 256);
        transpose_w_split<<<dim3(32, 32), 256, 0, s_s1>>>(wo, woTh, woTl, CD, CD);
        cudaEventRecord(s_ev1, s_s1);

        transpose_w<<<dim3(CF / 32, CD / 32, CE), 256, 0, s_s2>>>(w1, w1b, CD, CF);
        transpose_w<<<dim3(CF / 32, CD / 32, CE), 256, 0, s_s2>>>(w3, w3b, CD, CF);
        transpose_w<<<dim3(CD / 32, CF / 32, CE), 256, 0, s_s2>>>(w2, w2b, CF, CD);
        cudaEventRecord(s_ev2, s_s2);

        rmsnorm_split<<<CT, 256>>>(hid, ln1, xnbh, xnbl);
        cudaStreamWaitEvent(0, s_ev1, 0);
        qkv_b3<<<dim3(24, 16), 256, B3_SMEM>>>();
    } else {
        transpose_w_split<<<dim3(32, 32), 256>>>(wq, wqTh, wqTl, CD, CD);
        transpose_w_split<<<dim3(8, 32),  256>>>(wk, wkTh, wkTl, CD, 256);
        transpose_w_split<<<dim3(8, 32),  256>>>(wv, wvTh, wvTl, CD, 256);
        transpose_w_split<<<dim3(32, 32), 256>>>(wo, woTh, woTl, CD, CD);
        transpose_w<<<dim3(CF / 32, CD / 32, CE), 256>>>(w1, w1b, CD, CF);
        transpose_w<<<dim3(CF / 32, CD / 32, CE), 256>>>(w3, w3b, CD, CF);
        transpose_w<<<dim3(CD / 32, CF / 32, CE), 256>>>(w2, w2b, CF, CD);
        rmsnorm_split<<<CT, 256>>>(hid, ln1, xnbh, xnbl);
        qkv_b3<<<dim3(24, 16), 256, B3_SMEM>>>();
    }

    {
        int total = CT * (CH + CKV) * 32;
        rope_kernel<<<(total + 255) / 256, 256>>>(pos);
    }
    flash_bf16<<<dim3(CB * CH, CS / 128), 256, FL_SMEM>>>();
    oproj_b3<<<dim3(16, 16), 256, B3_SMEM>>>(hid);
    cudaMemsetAsync(cnt, 0, CE * sizeof(int));
    rmsnorm_router<<<CT, 256>>>(h1, ln2, gw, out_scores, hnb);

    if (par) cudaStreamWaitEvent(0, s_ev2, 0);

    moe_up_bf16<<<dim3(CF / 64, CT / 128, CE), 256, MOEUP_SMEM>>>();
    moe_down_bf16<<<dim3(CD / 64, CT / 128, CE), 256, MOEDN_SMEM>>>();
    combine_kernel<<<(CT * CD / 4 + 255) / 256, 256>>>(out);
}